// round 3
// baseline (speedup 1.0000x reference)
#include <cuda_runtime.h>
#include <cstdint>

#define NB   2
#define NC   512
#define NCQ  64
#define NPIX 4096

// ---------------- static device scratch (allocation-free) ----------------
__device__ float g_Q[NB][NCQ * NPIX];                 //  2 MB
__device__ float g_K[3][NB][NCQ * NPIX];              //  6 MB
__device__ float g_V[NB][NC * NPIX];                  // 16 MB
__device__ float g_E[6][(size_t)NPIX * NPIX];         // 402 MB : exp(S), idx z = br*2 + b
__device__ float g_invZ[6][NPIX];
__device__ float g_att[NB][NC * NPIX];                // 16 MB

// =====================================================================
// Projection GEMM: Out[M, NPIX] = W[M,512] @ X[512, NPIX] + bias[M]
// BM=64, BN=128, BK=16, 256 threads, 4x8 microtile. grid (32, M/64, NB)
// =====================================================================
template <int M>
__global__ __launch_bounds__(256) void proj_kernel(
    const float* __restrict__ W, const float* __restrict__ bias,
    const float* __restrict__ Xall, int which)
{
    float* Outall;
    if (which == 0)      Outall = &g_Q[0][0];
    else if (which <= 3) Outall = &g_K[which - 1][0][0];
    else                 Outall = &g_V[0][0];

    const int b = blockIdx.z;
    const float* X = Xall + (size_t)b * NC * NPIX;
    float* Out = Outall + (size_t)b * M * NPIX;

    const int m0 = blockIdx.y * 64;
    const int n0 = blockIdx.x * 128;

    __shared__ float As[16][64];
    __shared__ float Bs[16][128];

    const int tx   = threadIdx.x;
    const int trow = tx >> 4;          // 0..15 -> 4 rows each
    const int tcol = tx & 15;          // 0..15 -> 8 cols each
    const int ar   = tx >> 2;          // 0..63
    const int ac   = (tx & 3) << 2;    // 0,4,8,12
    const int br_  = tx >> 5;          // 0..7
    const int bc   = (tx & 31) << 2;   // 0..124

    float acc[4][8];
#pragma unroll
    for (int i = 0; i < 4; i++)
#pragma unroll
        for (int j = 0; j < 8; j++) acc[i][j] = 0.f;

    for (int k0 = 0; k0 < NC; k0 += 16) {
        float4 av = *(const float4*)(W + (size_t)(m0 + ar) * NC + k0 + ac);
        As[ac + 0][ar] = av.x;
        As[ac + 1][ar] = av.y;
        As[ac + 2][ar] = av.z;
        As[ac + 3][ar] = av.w;
        *(float4*)&Bs[br_][bc]     = *(const float4*)(X + (size_t)(k0 + br_) * NPIX + n0 + bc);
        *(float4*)&Bs[br_ + 8][bc] = *(const float4*)(X + (size_t)(k0 + br_ + 8) * NPIX + n0 + bc);
        __syncthreads();
#pragma unroll
        for (int kk = 0; kk < 16; kk++) {
            float a[4], bb[8];
            *(float4*)&a[0]  = *(const float4*)&As[kk][trow * 4];
            *(float4*)&bb[0] = *(const float4*)&Bs[kk][tcol * 8];
            *(float4*)&bb[4] = *(const float4*)&Bs[kk][tcol * 8 + 4];
#pragma unroll
            for (int i = 0; i < 4; i++)
#pragma unroll
                for (int j = 0; j < 8; j++) acc[i][j] += a[i] * bb[j];
        }
        __syncthreads();
    }
#pragma unroll
    for (int i = 0; i < 4; i++) {
        const int row = m0 + trow * 4 + i;
        const float bs = bias[row];
        float4 v0 = make_float4(acc[i][0] + bs, acc[i][1] + bs, acc[i][2] + bs, acc[i][3] + bs);
        float4 v1 = make_float4(acc[i][4] + bs, acc[i][5] + bs, acc[i][6] + bs, acc[i][7] + bs);
        float* p = Out + (size_t)row * NPIX + n0 + tcol * 8;
        *(float4*)p       = v0;
        *(float4*)(p + 4) = v1;
    }
}

// =====================================================================
// Scores: E[z][i][j] = exp( sum_c Q[b][c][i] * K[br][b][c][j] ), z = br*2+b
// M=N=4096, K=64. BM=BN=128, BK=8, 8x8 microtile. grid (32, 32, 6)
// =====================================================================
__global__ __launch_bounds__(256) void scores_kernel()
{
    const int z  = blockIdx.z;
    const int b  = z & 1;
    const int br = z >> 1;
    const float* __restrict__ Q  = &g_Q[b][0];
    const float* __restrict__ Kp = &g_K[br][b][0];
    float* __restrict__ E = &g_E[z][0];

    const int m0 = blockIdx.y * 128;
    const int n0 = blockIdx.x * 128;

    __shared__ float As[8][128];
    __shared__ float Bs[8][128];

    const int tx   = threadIdx.x;
    const int trow = tx >> 4;
    const int tcol = tx & 15;
    const int lr   = tx >> 5;          // 0..7
    const int lc   = (tx & 31) << 2;   // 0..124

    float acc[8][8] = {};

    for (int k0 = 0; k0 < NCQ; k0 += 8) {
        *(float4*)&As[lr][lc] = *(const float4*)(Q  + (size_t)(k0 + lr) * NPIX + m0 + lc);
        *(float4*)&Bs[lr][lc] = *(const float4*)(Kp + (size_t)(k0 + lr) * NPIX + n0 + lc);
        __syncthreads();
#pragma unroll
        for (int kk = 0; kk < 8; kk++) {
            float a[8], bb[8];
            *(float4*)&a[0]  = *(const float4*)&As[kk][trow * 8];
            *(float4*)&a[4]  = *(const float4*)&As[kk][trow * 8 + 4];
            *(float4*)&bb[0] = *(const float4*)&Bs[kk][tcol * 8];
            *(float4*)&bb[4] = *(const float4*)&Bs[kk][tcol * 8 + 4];
#pragma unroll
            for (int i = 0; i < 8; i++)
#pragma unroll
                for (int j = 0; j < 8; j++) acc[i][j] += a[i] * bb[j];
        }
        __syncthreads();
    }
#pragma unroll
    for (int i = 0; i < 8; i++) {
        float* p = E + (size_t)(m0 + trow * 8 + i) * NPIX + n0 + tcol * 8;
        float4 v0 = make_float4(__expf(acc[i][0]), __expf(acc[i][1]), __expf(acc[i][2]), __expf(acc[i][3]));
        float4 v1 = make_float4(__expf(acc[i][4]), __expf(acc[i][5]), __expf(acc[i][6]), __expf(acc[i][7]));
        *(float4*)p       = v0;
        *(float4*)(p + 4) = v1;
    }
}

// =====================================================================
// invZ[z][i] = 1 / sum_j E[z][i][j].  grid (4096, 6), 256 threads
// =====================================================================
__global__ __launch_bounds__(256) void invz_kernel()
{
    const int z   = blockIdx.y;
    const int row = blockIdx.x;
    const float4* __restrict__ E4 = (const float4*)(&g_E[z][0] + (size_t)row * NPIX);
    float s = 0.f;
    for (int j = threadIdx.x; j < NPIX / 4; j += 256) {
        float4 v = E4[j];
        s += (v.x + v.y) + (v.z + v.w);
    }
    __shared__ float red[256];
    red[threadIdx.x] = s;
    __syncthreads();
    for (int o = 128; o > 0; o >>= 1) {
        if (threadIdx.x < o) red[threadIdx.x] += red[threadIdx.x + o];
        __syncthreads();
    }
    if (threadIdx.x == 0) g_invZ[z][row] = 1.0f / red[0];
}

// =====================================================================
// att[b][c][j] = sum_br sum_i V[b][c][i]*invZ[z][i] * E[z][i][j]
// M=512, N=4096, K_eff = 3*4096 (branch loop inside). grid (32, 4, NB)
// =====================================================================
__global__ __launch_bounds__(256) void attn_gemm_kernel()
{
    const int b  = blockIdx.z;
    const int m0 = blockIdx.y * 128;
    const int n0 = blockIdx.x * 128;
    const float* __restrict__ V = &g_V[b][0];

    __shared__ float As[8][128];
    __shared__ float Bs[8][128];

    const int tx   = threadIdx.x;
    const int trow = tx >> 4;
    const int tcol = tx & 15;
    const int ar   = tx >> 1;          // 0..127
    const int ac   = (tx & 1) << 2;    // 0 or 4
    const int lr   = tx >> 5;
    const int lc   = (tx & 31) << 2;

    float acc[8][8] = {};

    for (int br = 0; br < 3; br++) {
        const int z = br * 2 + b;
        const float* __restrict__ E  = &g_E[z][0];
        const float* __restrict__ iz = &g_invZ[z][0];
        for (int k0 = 0; k0 < NPIX; k0 += 8) {
            float4 av = *(const float4*)(V + (size_t)(m0 + ar) * NPIX + k0 + ac);
            float4 zv = *(const float4*)(iz + k0 + ac);
            As[ac + 0][ar] = av.x * zv.x;
            As[ac + 1][ar] = av.y * zv.y;
            As[ac + 2][ar] = av.z * zv.z;
            As[ac + 3][ar] = av.w * zv.w;
            *(float4*)&Bs[lr][lc] = *(const float4*)(E + (size_t)(k0 + lr) * NPIX + n0 + lc);
            __syncthreads();
#pragma unroll
            for (int kk = 0; kk < 8; kk++) {
                float a[8], bb[8];
                *(float4*)&a[0]  = *(const float4*)&As[kk][trow * 8];
                *(float4*)&a[4]  = *(const float4*)&As[kk][trow * 8 + 4];
                *(float4*)&bb[0] = *(const float4*)&Bs[kk][tcol * 8];
                *(float4*)&bb[4] = *(const float4*)&Bs[kk][tcol * 8 + 4];
#pragma unroll
                for (int i = 0; i < 8; i++)
#pragma unroll
                    for (int j = 0; j < 8; j++) acc[i][j] += a[i] * bb[j];
            }
            __syncthreads();
        }
    }
    float* att = &g_att[b][0];
#pragma unroll
    for (int i = 0; i < 8; i++) {
        float* p = att + (size_t)(m0 + trow * 8 + i) * NPIX + n0 + tcol * 8;
        *(float4*)p       = make_float4(acc[i][0], acc[i][1], acc[i][2], acc[i][3]);
        *(float4*)(p + 4) = make_float4(acc[i][4], acc[i][5], acc[i][6], acc[i][7]);
    }
}

// =====================================================================
// out[b][c][n] = x[b][c][n] + gamma * ( sum_k Wl[c][k]*att[b][k][n] + bl[c] )
// M=512, N=4096, K=512. grid (32, 4, NB)
// =====================================================================
__global__ __launch_bounds__(256) void final_kernel(
    const float* __restrict__ Wl, const float* __restrict__ bl,
    const float* __restrict__ xin, const float* __restrict__ gamma,
    float* __restrict__ out)
{
    const int b  = blockIdx.z;
    const int m0 = blockIdx.y * 128;
    const int n0 = blockIdx.x * 128;
    const float* __restrict__ Att = &g_att[b][0];

    __shared__ float As[8][128];
    __shared__ float Bs[8][128];

    const int tx   = threadIdx.x;
    const int trow = tx >> 4;
    const int tcol = tx & 15;
    const int ar   = tx >> 1;
    const int ac   = (tx & 1) << 2;
    const int lr   = tx >> 5;
    const int lc   = (tx & 31) << 2;

    float acc[8][8] = {};

    for (int k0 = 0; k0 < NC; k0 += 8) {
        float4 av = *(const float4*)(Wl + (size_t)(m0 + ar) * NC + k0 + ac);
        As[ac + 0][ar] = av.x;
        As[ac + 1][ar] = av.y;
        As[ac + 2][ar] = av.z;
        As[ac + 3][ar] = av.w;
        *(float4*)&Bs[lr][lc] = *(const float4*)(Att + (size_t)(k0 + lr) * NPIX + n0 + lc);
        __syncthreads();
#pragma unroll
        for (int kk = 0; kk < 8; kk++) {
            float a[8], bb[8];
            *(float4*)&a[0]  = *(const float4*)&As[kk][trow * 8];
            *(float4*)&a[4]  = *(const float4*)&As[kk][trow * 8 + 4];
            *(float4*)&bb[0] = *(const float4*)&Bs[kk][tcol * 8];
            *(float4*)&bb[4] = *(const float4*)&Bs[kk][tcol * 8 + 4];
#pragma unroll
            for (int i = 0; i < 8; i++)
#pragma unroll
                for (int j = 0; j < 8; j++) acc[i][j] += a[i] * bb[j];
        }
        __syncthreads();
    }

    const float g = gamma[0];
#pragma unroll
    for (int i = 0; i < 8; i++) {
        const int row = m0 + trow * 8 + i;
        const float bs = bl[row];
        const size_t base = (size_t)b * NC * NPIX + (size_t)row * NPIX + n0 + tcol * 8;
        float4 x0 = *(const float4*)(xin + base);
        float4 x1 = *(const float4*)(xin + base + 4);
        float4 o0 = make_float4(x0.x + g * (acc[i][0] + bs), x0.y + g * (acc[i][1] + bs),
                                x0.z + g * (acc[i][2] + bs), x0.w + g * (acc[i][3] + bs));
        float4 o1 = make_float4(x1.x + g * (acc[i][4] + bs), x1.y + g * (acc[i][5] + bs),
                                x1.z + g * (acc[i][6] + bs), x1.w + g * (acc[i][7] + bs));
        *(float4*)(out + base)     = o0;
        *(float4*)(out + base + 4) = o1;
    }
}

// =====================================================================
extern "C" void kernel_launch(void* const* d_in, const int* in_sizes, int n_in,
                              void* d_out, int out_size)
{
    const float* x   = (const float*)d_in[0];
    const float* y   = (const float*)d_in[1];
    const float* zz  = (const float*)d_in[2];
    const float* Wq  = (const float*)d_in[3];
    const float* bq  = (const float*)d_in[4];
    const float* Wk1 = (const float*)d_in[5];
    const float* bk1 = (const float*)d_in[6];
    const float* Wk2 = (const float*)d_in[7];
    const float* bk2 = (const float*)d_in[8];
    const float* Wk3 = (const float*)d_in[9];
    const float* bk3 = (const float*)d_in[10];
    const float* Wv  = (const float*)d_in[11];
    const float* bv  = (const float*)d_in[12];
    const float* Wl  = (const float*)d_in[13];
    const float* bl  = (const float*)d_in[14];
    const float* gm  = (const float*)d_in[15];
    float* out = (float*)d_out;

    dim3 blk(256);
    proj_kernel<64> <<<dim3(32, 1, NB), blk>>>(Wq,  bq,  x,  0);
    proj_kernel<64> <<<dim3(32, 1, NB), blk>>>(Wk1, bk1, x,  1);
    proj_kernel<64> <<<dim3(32, 1, NB), blk>>>(Wk2, bk2, y,  2);
    proj_kernel<64> <<<dim3(32, 1, NB), blk>>>(Wk3, bk3, zz, 3);
    proj_kernel<512><<<dim3(32, 8, NB), blk>>>(Wv,  bv,  x,  4);

    scores_kernel<<<dim3(32, 32, 6), blk>>>();
    invz_kernel  <<<dim3(NPIX, 6),   blk>>>();
    attn_gemm_kernel<<<dim3(32, 4, NB), blk>>>();
    final_kernel <<<dim3(32, 4, NB), blk>>>(Wl, bl, x, gm, out);
}

// round 5
// speedup vs baseline: 3.2486x; 3.2486x over previous
#include <cuda_runtime.h>
#include <cuda_bf16.h>
#include <cstdint>

#define NB   2
#define NC   512
#define NCQ  64
#define NPIX 4096
#define KTOT 12288   // 3 branches * NPIX

// ---------------- static device scratch (allocation-free) ----------------
__device__ float g_Q[NB][NCQ * NPIX];                       //  2 MB
__device__ float g_K[3][NB][NCQ * NPIX];                    //  6 MB
__device__ float g_V[NB][NC * NPIX];                        // 16 MB
__device__ __nv_bfloat16 g_Et[6][(size_t)NPIX * NPIX];      // 201 MB  Et[z][j][i]=exp(S[i][j])
__device__ float g_Zsum[6][NPIX];
__device__ float g_invZ[6][NPIX];
__device__ __nv_bfloat16 g_Abf[NB][(size_t)NC * KTOT];      //  25 MB  A[c][br*4096+k] = V*invZ
__device__ float g_att[NB][NC * NPIX];                      //  16 MB

__device__ __forceinline__ uint32_t smem_u32(const void* p) {
    uint32_t a;
    asm("{ .reg .u64 t; cvta.to.shared.u64 t, %1; cvt.u32.u64 %0, t; }" : "=r"(a) : "l"(p));
    return a;
}

// =====================================================================
// Fused small projections: sel 0:Q(x) 1:K1(x) 2:K2(y) 3:K3(z). M=64.
// grid (32, 4, NB), 256 threads
// =====================================================================
__global__ __launch_bounds__(256) void proj_qk_kernel(
    const float* __restrict__ Wq,  const float* __restrict__ bq,
    const float* __restrict__ Wk1, const float* __restrict__ bk1,
    const float* __restrict__ Wk2, const float* __restrict__ bk2,
    const float* __restrict__ Wk3, const float* __restrict__ bk3,
    const float* __restrict__ x, const float* __restrict__ y, const float* __restrict__ z)
{
    const int sel = blockIdx.y;
    const float *W, *bias, *Xall; float* Outall;
    if      (sel == 0) { W = Wq;  bias = bq;  Xall = x; Outall = &g_Q[0][0]; }
    else if (sel == 1) { W = Wk1; bias = bk1; Xall = x; Outall = &g_K[0][0][0]; }
    else if (sel == 2) { W = Wk2; bias = bk2; Xall = y; Outall = &g_K[1][0][0]; }
    else               { W = Wk3; bias = bk3; Xall = z; Outall = &g_K[2][0][0]; }

    const int b = blockIdx.z;
    const float* X = Xall + (size_t)b * NC * NPIX;
    float* Out = Outall + (size_t)b * NCQ * NPIX;
    const int n0 = blockIdx.x * 128;

    __shared__ float As[16][64];
    __shared__ float Bs[16][128];

    const int tx = threadIdx.x;
    const int trow = tx >> 4, tcol = tx & 15;
    const int ar = tx >> 2, ac = (tx & 3) << 2;
    const int br_ = tx >> 5, bc = (tx & 31) << 2;

    float acc[4][8] = {};
    for (int k0 = 0; k0 < NC; k0 += 16) {
        float4 av = *(const float4*)(W + (size_t)ar * NC + k0 + ac);
        As[ac + 0][ar] = av.x; As[ac + 1][ar] = av.y;
        As[ac + 2][ar] = av.z; As[ac + 3][ar] = av.w;
        *(float4*)&Bs[br_][bc]     = *(const float4*)(X + (size_t)(k0 + br_) * NPIX + n0 + bc);
        *(float4*)&Bs[br_ + 8][bc] = *(const float4*)(X + (size_t)(k0 + br_ + 8) * NPIX + n0 + bc);
        __syncthreads();
#pragma unroll
        for (int kk = 0; kk < 16; kk++) {
            float a[4], bb[8];
            *(float4*)&a[0]  = *(const float4*)&As[kk][trow * 4];
            *(float4*)&bb[0] = *(const float4*)&Bs[kk][tcol * 8];
            *(float4*)&bb[4] = *(const float4*)&Bs[kk][tcol * 8 + 4];
#pragma unroll
            for (int i = 0; i < 4; i++)
#pragma unroll
                for (int j = 0; j < 8; j++) acc[i][j] += a[i] * bb[j];
        }
        __syncthreads();
    }
#pragma unroll
    for (int i = 0; i < 4; i++) {
        const int row = trow * 4 + i;
        const float bs = bias[row];
        float* p = Out + (size_t)row * NPIX + n0 + tcol * 8;
        *(float4*)p       = make_float4(acc[i][0] + bs, acc[i][1] + bs, acc[i][2] + bs, acc[i][3] + bs);
        *(float4*)(p + 4) = make_float4(acc[i][4] + bs, acc[i][5] + bs, acc[i][6] + bs, acc[i][7] + bs);
    }
}

// =====================================================================
// V projection: M=512. grid (32, 8, NB), 256 threads
// =====================================================================
__global__ __launch_bounds__(256) void proj_v_kernel(
    const float* __restrict__ Wv, const float* __restrict__ bv,
    const float* __restrict__ x)
{
    const int b = blockIdx.z;
    const float* X = x + (size_t)b * NC * NPIX;
    float* Out = &g_V[b][0];
    const int m0 = blockIdx.y * 64;
    const int n0 = blockIdx.x * 128;

    __shared__ float As[16][64];
    __shared__ float Bs[16][128];

    const int tx = threadIdx.x;
    const int trow = tx >> 4, tcol = tx & 15;
    const int ar = tx >> 2, ac = (tx & 3) << 2;
    const int br_ = tx >> 5, bc = (tx & 31) << 2;

    float acc[4][8] = {};
    for (int k0 = 0; k0 < NC; k0 += 16) {
        float4 av = *(const float4*)(Wv + (size_t)(m0 + ar) * NC + k0 + ac);
        As[ac + 0][ar] = av.x; As[ac + 1][ar] = av.y;
        As[ac + 2][ar] = av.z; As[ac + 3][ar] = av.w;
        *(float4*)&Bs[br_][bc]     = *(const float4*)(X + (size_t)(k0 + br_) * NPIX + n0 + bc);
        *(float4*)&Bs[br_ + 8][bc] = *(const float4*)(X + (size_t)(k0 + br_ + 8) * NPIX + n0 + bc);
        __syncthreads();
#pragma unroll
        for (int kk = 0; kk < 16; kk++) {
            float a[4], bb[8];
            *(float4*)&a[0]  = *(const float4*)&As[kk][trow * 4];
            *(float4*)&bb[0] = *(const float4*)&Bs[kk][tcol * 8];
            *(float4*)&bb[4] = *(const float4*)&Bs[kk][tcol * 8 + 4];
#pragma unroll
            for (int i = 0; i < 4; i++)
#pragma unroll
                for (int j = 0; j < 8; j++) acc[i][j] += a[i] * bb[j];
        }
        __syncthreads();
    }
#pragma unroll
    for (int i = 0; i < 4; i++) {
        const int row = m0 + trow * 4 + i;
        const float bs = bv[row];
        float* p = Out + (size_t)row * NPIX + n0 + tcol * 8;
        *(float4*)p       = make_float4(acc[i][0] + bs, acc[i][1] + bs, acc[i][2] + bs, acc[i][3] + bs);
        *(float4*)(p + 4) = make_float4(acc[i][4] + bs, acc[i][5] + bs, acc[i][6] + bs, acc[i][7] + bs);
    }
}

// =====================================================================
// Scores transposed: Et[z][m][n] = exp( sum_c K[c][m] * Q[c][n] ), bf16 out
// grid (32, 32, 6), 256 threads
// =====================================================================
__global__ __launch_bounds__(256) void scores_kernel()
{
    const int zz = blockIdx.z;
    const int b = zz & 1, br = zz >> 1;
    const float* __restrict__ Kp = &g_K[br][b][0];   // rows (m = key pixel)
    const float* __restrict__ Q  = &g_Q[b][0];       // cols (n = query pixel)
    __nv_bfloat16* __restrict__ E = &g_Et[zz][0];

    const int m0 = blockIdx.y * 128;
    const int n0 = blockIdx.x * 128;

    __shared__ float As[8][128];
    __shared__ float Bs[8][128];

    const int tx = threadIdx.x;
    const int trow = tx >> 4, tcol = tx & 15;
    const int lr = tx >> 5, lc = (tx & 31) << 2;

    float acc[8][8] = {};
    for (int k0 = 0; k0 < NCQ; k0 += 8) {
        *(float4*)&As[lr][lc] = *(const float4*)(Kp + (size_t)(k0 + lr) * NPIX + m0 + lc);
        *(float4*)&Bs[lr][lc] = *(const float4*)(Q  + (size_t)(k0 + lr) * NPIX + n0 + lc);
        __syncthreads();
#pragma unroll
        for (int kk = 0; kk < 8; kk++) {
            float a[8], bb[8];
            *(float4*)&a[0]  = *(const float4*)&As[kk][trow * 8];
            *(float4*)&a[4]  = *(const float4*)&As[kk][trow * 8 + 4];
            *(float4*)&bb[0] = *(const float4*)&Bs[kk][tcol * 8];
            *(float4*)&bb[4] = *(const float4*)&Bs[kk][tcol * 8 + 4];
#pragma unroll
            for (int i = 0; i < 8; i++)
#pragma unroll
                for (int j = 0; j < 8; j++) acc[i][j] += a[i] * bb[j];
        }
        __syncthreads();
    }
#pragma unroll
    for (int i = 0; i < 8; i++) {
        union { __nv_bfloat162 h2[4]; uint4 v; } t;
#pragma unroll
        for (int j = 0; j < 4; j++)
            t.h2[j] = __floats2bfloat162_rn(__expf(acc[i][2 * j]), __expf(acc[i][2 * j + 1]));
        *(uint4*)(E + (size_t)(m0 + trow * 8 + i) * NPIX + n0 + tcol * 8) = t.v;
    }
}

// ===================== Z = column sums of Et (softmax denominator) =====================
__global__ __launch_bounds__(1024) void zeroZ_kernel()
{
    const int zz = blockIdx.x;
#pragma unroll
    for (int k = 0; k < 4; k++) g_Zsum[zz][threadIdx.x + k * 1024] = 0.f;
}

__global__ __launch_bounds__(256) void partialZ_kernel()
{
    // grid (8, 8, 6): 512 cols x 512 rows per block
    const int zz = blockIdx.z;
    const int i0 = blockIdx.x * 512 + threadIdx.x * 2;
    const int j0 = blockIdx.y * 512;
    const __nv_bfloat16* p = &g_Et[zz][0] + (size_t)j0 * NPIX + i0;
    float s0 = 0.f, s1 = 0.f;
    for (int j = 0; j < 512; j++) {
        __nv_bfloat162 v = *(const __nv_bfloat162*)(p + (size_t)j * NPIX);
        s0 += __bfloat162float(v.x);
        s1 += __bfloat162float(v.y);
    }
    atomicAdd(&g_Zsum[zz][i0], s0);
    atomicAdd(&g_Zsum[zz][i0 + 1], s1);
}

__global__ __launch_bounds__(1024) void invertZ_kernel()
{
    const int zz = blockIdx.x;
#pragma unroll
    for (int k = 0; k < 4; k++) {
        const int i = threadIdx.x + k * 1024;
        g_invZ[zz][i] = 1.0f / g_Zsum[zz][i];
    }
}

// ===================== A = bf16(V * invZ), [NC, KTOT] per batch =====================
__global__ __launch_bounds__(256) void convertA_kernel()
{
    // grid (6, 512, 2)
    const int b = blockIdx.z, c = blockIdx.y;
    const int base = blockIdx.x * 2048 + threadIdx.x * 8;  // col in [0, 12288)
    const int br = base >> 12;
    const int i = base & 4095;
    const float* Vp = &g_V[b][0] + (size_t)c * NPIX + i;
    const float* iz = &g_invZ[br * 2 + b][0] + i;
    float4 v0 = *(const float4*)Vp, v1 = *(const float4*)(Vp + 4);
    float4 z0 = *(const float4*)iz, z1 = *(const float4*)(iz + 4);
    union { __nv_bfloat162 h2[4]; uint4 v; } t;
    t.h2[0] = __floats2bfloat162_rn(v0.x * z0.x, v0.y * z0.y);
    t.h2[1] = __floats2bfloat162_rn(v0.z * z0.z, v0.w * z0.w);
    t.h2[2] = __floats2bfloat162_rn(v1.x * z1.x, v1.y * z1.y);
    t.h2[3] = __floats2bfloat162_rn(v1.z * z1.z, v1.w * z1.w);
    *(uint4*)(&g_Abf[b][0] + (size_t)c * KTOT + base) = t.v;
}

// =====================================================================
// Aggregation GEMM on HMMA (mma.sync bf16):
//   att[b][c][n] = sum_k Abf[b][c][k] * Et[.][n][k]   (k over 3*4096)
// Block 128x128, BK=32, 8 warps (2x4), warp tile 64x32.
// Padded SMEM stride 40 bf16 (80B) -> conflict-free ldmatrix.
// cp.async double-buffered. grid (32, 4, NB), 256 threads.
// =====================================================================
#define SA 40   // smem row stride in bf16 elements

__global__ __launch_bounds__(256, 2) void attn_mma_kernel()
{
    __shared__ __nv_bfloat16 smA[2][128 * SA];
    __shared__ __nv_bfloat16 smB[2][128 * SA];

    const int tid = threadIdx.x;
    const int wid = tid >> 5, lane = tid & 31;
    const int b = blockIdx.z;
    const int m0 = blockIdx.y * 128;
    const int n0 = blockIdx.x * 128;

    const __nv_bfloat16* __restrict__ Ag = &g_Abf[b][0];

    const int wr = wid & 1;        // 0..1 -> m offset
    const int wc = wid >> 1;       // 0..3 -> n offset
    const int wm = wr * 64;
    const int wn = wc * 32;

    float acc[4][4][4];
#pragma unroll
    for (int i = 0; i < 4; i++)
#pragma unroll
        for (int j = 0; j < 4; j++)
#pragma unroll
            for (int q = 0; q < 4; q++) acc[i][j][q] = 0.f;

    const uint32_t sA0 = smem_u32(&smA[0][0]);
    const uint32_t sB0 = smem_u32(&smB[0][0]);

    // per-thread gmem->smem chunk mapping: 2 chunks of 16B per matrix per stage
    const int row0 = tid >> 2;              // 0..63
    const int cc0  = tid & 3;               // chunk col 0..3 (16B each = 8 bf16)
    // second chunk: row0+64

    // ldmatrix addresses (byte offsets within a stage)
    const int la_row = wm + (lane & 15);
    const int la_col = (lane >> 4) << 3;    // 0 or 8
    const uint32_t a_off = (uint32_t)(la_row * SA + la_col) * 2;
    const int lb_row = wn + (lane & 7);
    const int lb_col = ((lane >> 3) & 1) << 3;
    const uint32_t b_off = (uint32_t)(lb_row * SA + lb_col) * 2;

    const int NT = KTOT / 32;  // 384

    // ---- prologue: stage 0 ----
    {
        const int kg = 0;
        const __nv_bfloat16* Bg = &g_Et[b][0];  // br=0 -> z = b
#pragma unroll
        for (int h = 0; h < 2; h++) {
            const int row = row0 + h * 64;
            const uint32_t dA = sA0 + (uint32_t)(row * SA + cc0 * 8) * 2;
            const uint32_t dB = sB0 + (uint32_t)(row * SA + cc0 * 8) * 2;
            const void* srcA = Ag + (size_t)(m0 + row) * KTOT + kg + cc0 * 8;
            const void* srcB = Bg + (size_t)(n0 + row) * NPIX + kg + cc0 * 8;
            asm volatile("cp.async.cg.shared.global [%0], [%1], 16;" :: "r"(dA), "l"(srcA) : "memory");
            asm volatile("cp.async.cg.shared.global [%0], [%1], 16;" :: "r"(dB), "l"(srcB) : "memory");
        }
        asm volatile("cp.async.commit_group;" ::: "memory");
    }

    for (int kt = 0; kt < NT; ++kt) {
        const int s = kt & 1;
        if (kt + 1 < NT) {
            const int kg = (kt + 1) << 5;
            const int br = kg >> 12;
            const int kloc = kg & 4095;
            const __nv_bfloat16* __restrict__ Bg = &g_Et[br * 2 + b][0];
            const uint32_t stoff = (uint32_t)((s ^ 1) * 128 * SA * 2);
#pragma unroll
            for (int h = 0; h < 2; h++) {
                const int row = row0 + h * 64;
                const uint32_t dA = sA0 + stoff + (uint32_t)(row * SA + cc0 * 8) * 2;
                const uint32_t dB = sB0 + stoff + (uint32_t)(row * SA + cc0 * 8) * 2;
                const void* srcA = Ag + (size_t)(m0 + row) * KTOT + kg + cc0 * 8;
                const void* srcB = Bg + (size_t)(n0 + row) * NPIX + kloc + cc0 * 8;
                asm volatile("cp.async.cg.shared.global [%0], [%1], 16;" :: "r"(dA), "l"(srcA) : "memory");
                asm volatile("cp.async.cg.shared.global [%0], [%1], 16;" :: "r"(dB), "l"(srcB) : "memory");
            }
            asm volatile("cp.async.commit_group;" ::: "memory");
            asm volatile("cp.async.wait_group 1;" ::: "memory");
        } else {
            asm volatile("cp.async.wait_group 0;" ::: "memory");
        }
        __syncthreads();

        const uint32_t stA = sA0 + (uint32_t)(s * 128 * SA * 2);
        const uint32_t stB = sB0 + (uint32_t)(s * 128 * SA * 2);

#pragma unroll
        for (int ks = 0; ks < 2; ks++) {
            uint32_t af[4][4];
#pragma unroll
            for (int mt = 0; mt < 4; mt++) {
                const uint32_t addr = stA + a_off + (uint32_t)(ks * 16) * 2 + (uint32_t)(mt * 16 * SA) * 2;
                asm volatile("ldmatrix.sync.aligned.m8n8.x4.shared.b16 {%0,%1,%2,%3}, [%4];"
                             : "=r"(af[mt][0]), "=r"(af[mt][1]), "=r"(af[mt][2]), "=r"(af[mt][3])
                             : "r"(addr));
            }
            uint32_t bf[4][2];
#pragma unroll
            for (int nt = 0; nt < 4; nt++) {
                const uint32_t addr = stB + b_off + (uint32_t)(ks * 16) * 2 + (uint32_t)(nt * 8 * SA) * 2;
                asm volatile("ldmatrix.sync.aligned.m8n8.x2.shared.b16 {%0,%1}, [%2];"
                             : "=r"(bf[nt][0]), "=r"(bf[nt][1])
                             : "r"(addr));
            }
#pragma unroll
            for (int mt = 0; mt < 4; mt++)
#pragma unroll
                for (int nt = 0; nt < 4; nt++) {
                    asm volatile(
                        "mma.sync.aligned.m16n8k16.row.col.f32.bf16.bf16.f32 "
                        "{%0,%1,%2,%3}, {%4,%5,%6,%7}, {%8,%9}, {%0,%1,%2,%3};"
                        : "+f"(acc[mt][nt][0]), "+f"(acc[mt][nt][1]),
                          "+f"(acc[mt][nt][2]), "+f"(acc[mt][nt][3])
                        : "r"(af[mt][0]), "r"(af[mt][1]), "r"(af[mt][2]), "r"(af[mt][3]),
                          "r"(bf[nt][0]), "r"(bf[nt][1]));
                }
        }
        __syncthreads();
    }

    // epilogue: store acc to g_att (fp32)
    float* __restrict__ att = &g_att[b][0];
    const int erow = lane >> 2;
    const int ecol = (lane & 3) * 2;
#pragma unroll
    for (int mt = 0; mt < 4; mt++) {
#pragma unroll
        for (int nt = 0; nt < 4; nt++) {
            const int r0 = m0 + wm + mt * 16 + erow;
            const int c0 = n0 + wn + nt * 8 + ecol;
            *(float2*)(att + (size_t)r0 * NPIX + c0)       = make_float2(acc[mt][nt][0], acc[mt][nt][1]);
            *(float2*)(att + (size_t)(r0 + 8) * NPIX + c0) = make_float2(acc[mt][nt][2], acc[mt][nt][3]);
        }
    }
}

// =====================================================================
// out = x + gamma * (Wl @ att + bl). M=512, N=4096, K=512. grid (32, 4, NB)
// =====================================================================
__global__ __launch_bounds__(256) void final_kernel(
    const float* __restrict__ Wl, const float* __restrict__ bl,
    const float* __restrict__ xin, const float* __restrict__ gamma,
    float* __restrict__ out)
{
    const int b = blockIdx.z;
    const int m0 = blockIdx.y * 128;
    const int n0 = blockIdx.x * 128;
    const float* __restrict__ Att = &g_att[b][0];

    __shared__ float As[8][128];
    __shared__ float Bs[8][128];

    const int tx = threadIdx.x;
    const int trow = tx >> 4, tcol = tx & 15;
    const int ar = tx >> 1, ac = (tx & 1) << 2;
    const int lr = tx >> 5, lc = (tx & 31) << 2;

    float acc[8][8] = {};
    for (int k0 = 0; k0 < NC; k0 += 8) {
        float4 av = *(const float4*)(Wl + (size_t)(m0 + ar) * NC + k0 + ac);
        As[ac + 0][ar] = av.x; As[ac + 1][ar] = av.y;
        As[ac + 2][ar] = av.z; As[ac + 3][ar] = av.w;
        *(float4*)&Bs[lr][lc] = *(const float4*)(Att + (size_t)(k0 + lr) * NPIX + n0 + lc);
        __syncthreads();
#pragma unroll
        for (int kk = 0; kk < 8; kk++) {
            float a[8], bb[8];
            *(float4*)&a[0]  = *(const float4*)&As[kk][trow * 8];
            *(float4*)&a[4]  = *(const float4*)&As[kk][trow * 8 + 4];
            *(float4*)&bb[0] = *(const float4*)&Bs[kk][tcol * 8];
            *(float4*)&bb[4] = *(const float4*)&Bs[kk][tcol * 8 + 4];
#pragma unroll
            for (int i = 0; i < 8; i++)
#pragma unroll
                for (int j = 0; j < 8; j++) acc[i][j] += a[i] * bb[j];
        }
        __syncthreads();
    }

    const float g = gamma[0];
#pragma unroll
    for (int i = 0; i < 8; i++) {
        const int row = m0 + trow * 8 + i;
        const float bs = bl[row];
        const size_t base = (size_t)b * NC * NPIX + (size_t)row * NPIX + n0 + tcol * 8;
        float4 x0 = *(const float4*)(xin + base);
        float4 x1 = *(const float4*)(xin + base + 4);
        *(float4*)(out + base) = make_float4(
            x0.x + g * (acc[i][0] + bs), x0.y + g * (acc[i][1] + bs),
            x0.z + g * (acc[i][2] + bs), x0.w + g * (acc[i][3] + bs));
        *(float4*)(out + base + 4) = make_float4(
            x1.x + g * (acc[i][4] + bs), x1.y + g * (acc[i][5] + bs),
            x1.z + g * (acc[i][6] + bs), x1.w + g * (acc[i][7] + bs));
    }
}

// =====================================================================
extern "C" void kernel_launch(void* const* d_in, const int* in_sizes, int n_in,
                              void* d_out, int out_size)
{
    const float* x   = (const float*)d_in[0];
    const float* y   = (const float*)d_in[1];
    const float* zz  = (const float*)d_in[2];
    const float* Wq  = (const float*)d_in[3];
    const float* bq  = (const float*)d_in[4];
    const float* Wk1 = (const float*)d_in[5];
    const float* bk1 = (const float*)d_in[6];
    const float* Wk2 = (const float*)d_in[7];
    const float* bk2 = (const float*)d_in[8];
    const float* Wk3 = (const float*)d_in[9];
    const float* bk3 = (const float*)d_in[10];
    const float* Wv  = (const float*)d_in[11];
    const float* bv  = (const float*)d_in[12];
    const float* Wl  = (const float*)d_in[13];
    const float* bl  = (const float*)d_in[14];
    const float* gm  = (const float*)d_in[15];
    float* out = (float*)d_out;

    dim3 blk(256);
    zeroZ_kernel<<<6, 1024>>>();
    proj_qk_kernel<<<dim3(32, 4, NB), blk>>>(Wq, bq, Wk1, bk1, Wk2, bk2, Wk3, bk3, x, y, zz);
    proj_v_kernel <<<dim3(32, 8, NB), blk>>>(Wv, bv, x);
    scores_kernel <<<dim3(32, 32, 6), blk>>>();
    partialZ_kernel<<<dim3(8, 8, 6), blk>>>();
    invertZ_kernel<<<6, 1024>>>();
    convertA_kernel<<<dim3(6, 512, NB), blk>>>();
    attn_mma_kernel<<<dim3(32, 4, NB), blk>>>();
    final_kernel  <<<dim3(32, 4, NB), blk>>>(Wl, bl, x, gm, out);
}

// round 6
// speedup vs baseline: 3.7621x; 1.1581x over previous
#include <cuda_runtime.h>
#include <cuda_bf16.h>
#include <cstdint>

#define NB   2
#define NC   512
#define NCQ  64
#define NPIX 4096
#define KTOT 12288   // 3 branches * NPIX

// ---------------- static device scratch (allocation-free) ----------------
__device__ float g_Q[NB][NCQ * NPIX];                       //  2 MB
__device__ float g_K[3][NB][NCQ * NPIX];                    //  6 MB
__device__ __nv_bfloat16 g_Qt[NB][NPIX * NCQ];              //  1 MB  Qt[i][c]
__device__ __nv_bfloat16 g_Kt[3][NB][NPIX * NCQ];           //  3 MB  Kt[j][c]
__device__ float g_V[NB][NC * NPIX];                        // 16 MB
__device__ __nv_bfloat16 g_Et[6][(size_t)NPIX * NPIX];      // 201 MB  Et[z][j][i]=exp(S[i][j])
__device__ float g_Zsum[6][NPIX];
__device__ float g_invZ[6][NPIX];
__device__ __nv_bfloat16 g_Abf[NB][(size_t)NC * KTOT];      //  25 MB  A[c][br*4096+k] = V*invZ
__device__ float g_att[NB][NC * NPIX];                      //  16 MB

__device__ __forceinline__ uint32_t smem_u32(const void* p) {
    uint32_t a;
    asm("{ .reg .u64 t; cvta.to.shared.u64 t, %1; cvt.u32.u64 %0, t; }" : "=r"(a) : "l"(p));
    return a;
}

// =====================================================================
// Fused small projections: sel 0:Q(x) 1:K1(x) 2:K2(y) 3:K3(z). M=64.
// grid (32, 4, NB), 256 threads
// =====================================================================
__global__ __launch_bounds__(256) void proj_qk_kernel(
    const float* __restrict__ Wq,  const float* __restrict__ bq,
    const float* __restrict__ Wk1, const float* __restrict__ bk1,
    const float* __restrict__ Wk2, const float* __restrict__ bk2,
    const float* __restrict__ Wk3, const float* __restrict__ bk3,
    const float* __restrict__ x, const float* __restrict__ y, const float* __restrict__ z)
{
    const int sel = blockIdx.y;
    const float *W, *bias, *Xall; float* Outall;
    if      (sel == 0) { W = Wq;  bias = bq;  Xall = x; Outall = &g_Q[0][0]; }
    else if (sel == 1) { W = Wk1; bias = bk1; Xall = x; Outall = &g_K[0][0][0]; }
    else if (sel == 2) { W = Wk2; bias = bk2; Xall = y; Outall = &g_K[1][0][0]; }
    else               { W = Wk3; bias = bk3; Xall = z; Outall = &g_K[2][0][0]; }

    const int b = blockIdx.z;
    const float* X = Xall + (size_t)b * NC * NPIX;
    float* Out = Outall + (size_t)b * NCQ * NPIX;
    const int n0 = blockIdx.x * 128;

    __shared__ float As[16][64];
    __shared__ float Bs[16][128];

    const int tx = threadIdx.x;
    const int trow = tx >> 4, tcol = tx & 15;
    const int ar = tx >> 2, ac = (tx & 3) << 2;
    const int br_ = tx >> 5, bc = (tx & 31) << 2;

    float acc[4][8] = {};
    for (int k0 = 0; k0 < NC; k0 += 16) {
        float4 av = *(const float4*)(W + (size_t)ar * NC + k0 + ac);
        As[ac + 0][ar] = av.x; As[ac + 1][ar] = av.y;
        As[ac + 2][ar] = av.z; As[ac + 3][ar] = av.w;
        *(float4*)&Bs[br_][bc]     = *(const float4*)(X + (size_t)(k0 + br_) * NPIX + n0 + bc);
        *(float4*)&Bs[br_ + 8][bc] = *(const float4*)(X + (size_t)(k0 + br_ + 8) * NPIX + n0 + bc);
        __syncthreads();
#pragma unroll
        for (int kk = 0; kk < 16; kk++) {
            float a[4], bb[8];
            *(float4*)&a[0]  = *(const float4*)&As[kk][trow * 4];
            *(float4*)&bb[0] = *(const float4*)&Bs[kk][tcol * 8];
            *(float4*)&bb[4] = *(const float4*)&Bs[kk][tcol * 8 + 4];
#pragma unroll
            for (int i = 0; i < 4; i++)
#pragma unroll
                for (int j = 0; j < 8; j++) acc[i][j] += a[i] * bb[j];
        }
        __syncthreads();
    }
#pragma unroll
    for (int i = 0; i < 4; i++) {
        const int row = trow * 4 + i;
        const float bs = bias[row];
        float* p = Out + (size_t)row * NPIX + n0 + tcol * 8;
        *(float4*)p       = make_float4(acc[i][0] + bs, acc[i][1] + bs, acc[i][2] + bs, acc[i][3] + bs);
        *(float4*)(p + 4) = make_float4(acc[i][4] + bs, acc[i][5] + bs, acc[i][6] + bs, acc[i][7] + bs);
    }
}

// =====================================================================
// Transpose+convert Q/K -> bf16 [pixel][64]: plane p: t=p>>1 (0=Q,1..3=K), b=p&1
// grid (128, 2, 8), block (32, 8)
// =====================================================================
__global__ __launch_bounds__(256) void transposeQK_kernel()
{
    const int p = blockIdx.z;
    const int t = p >> 1, b = p & 1;
    const float* in = (t == 0) ? &g_Q[b][0] : &g_K[t - 1][b][0];
    __nv_bfloat16* out = (t == 0) ? &g_Qt[b][0] : &g_Kt[t - 1][b][0];

    __shared__ float sm[32][33];
    const int p0 = blockIdx.x * 32;
    const int c0 = blockIdx.y * 32;
    const int tx = threadIdx.x, ty = threadIdx.y;
#pragma unroll
    for (int i = 0; i < 4; i++)
        sm[ty + i * 8][tx] = in[(size_t)(c0 + ty + i * 8) * NPIX + p0 + tx];
    __syncthreads();
#pragma unroll
    for (int i = 0; i < 4; i++)
        out[(size_t)(p0 + ty + i * 8) * NCQ + c0 + tx] = __float2bfloat16(sm[tx][ty + i * 8]);
}

// =====================================================================
// V projection: M=512. grid (32, 8, NB), 256 threads
// =====================================================================
__global__ __launch_bounds__(256) void proj_v_kernel(
    const float* __restrict__ Wv, const float* __restrict__ bv,
    const float* __restrict__ x)
{
    const int b = blockIdx.z;
    const float* X = x + (size_t)b * NC * NPIX;
    float* Out = &g_V[b][0];
    const int m0 = blockIdx.y * 64;
    const int n0 = blockIdx.x * 128;

    __shared__ float As[16][64];
    __shared__ float Bs[16][128];

    const int tx = threadIdx.x;
    const int trow = tx >> 4, tcol = tx & 15;
    const int ar = tx >> 2, ac = (tx & 3) << 2;
    const int br_ = tx >> 5, bc = (tx & 31) << 2;

    float acc[4][8] = {};
    for (int k0 = 0; k0 < NC; k0 += 16) {
        float4 av = *(const float4*)(Wv + (size_t)(m0 + ar) * NC + k0 + ac);
        As[ac + 0][ar] = av.x; As[ac + 1][ar] = av.y;
        As[ac + 2][ar] = av.z; As[ac + 3][ar] = av.w;
        *(float4*)&Bs[br_][bc]     = *(const float4*)(X + (size_t)(k0 + br_) * NPIX + n0 + bc);
        *(float4*)&Bs[br_ + 8][bc] = *(const float4*)(X + (size_t)(k0 + br_ + 8) * NPIX + n0 + bc);
        __syncthreads();
#pragma unroll
        for (int kk = 0; kk < 16; kk++) {
            float a[4], bb[8];
            *(float4*)&a[0]  = *(const float4*)&As[kk][trow * 4];
            *(float4*)&bb[0] = *(const float4*)&Bs[kk][tcol * 8];
            *(float4*)&bb[4] = *(const float4*)&Bs[kk][tcol * 8 + 4];
#pragma unroll
            for (int i = 0; i < 4; i++)
#pragma unroll
                for (int j = 0; j < 8; j++) acc[i][j] += a[i] * bb[j];
        }
        __syncthreads();
    }
#pragma unroll
    for (int i = 0; i < 4; i++) {
        const int row = m0 + trow * 4 + i;
        const float bs = bv[row];
        float* p = Out + (size_t)row * NPIX + n0 + tcol * 8;
        *(float4*)p       = make_float4(acc[i][0] + bs, acc[i][1] + bs, acc[i][2] + bs, acc[i][3] + bs);
        *(float4*)(p + 4) = make_float4(acc[i][4] + bs, acc[i][5] + bs, acc[i][6] + bs, acc[i][7] + bs);
    }
}

// =====================================================================
// Scores via HMMA + fused column-sum:
//   Et[z][m][n] = exp( sum_c Kt[m][c] * Qt[n][c] ), Zsum[z][n] += col sums
// 128x128x64 per block, 8 warps 2x4, warp 64x32. grid (32, 32, 6)
// =====================================================================
#define SCB 72   // smem row stride (bf16) for 64-col tiles

__global__ __launch_bounds__(256, 2) void scores_mma_kernel()
{
    __shared__ __nv_bfloat16 smA[128 * SCB];
    __shared__ __nv_bfloat16 smB[128 * SCB];
    __shared__ float cs[128];

    const int tid = threadIdx.x;
    const int wid = tid >> 5, lane = tid & 31;
    const int zz = blockIdx.z;
    const int b = zz & 1, br = zz >> 1;
    const int m0 = blockIdx.y * 128;   // key pixel j
    const int n0 = blockIdx.x * 128;   // query pixel i

    const __nv_bfloat16* __restrict__ Ag = &g_Kt[br][b][0];
    const __nv_bfloat16* __restrict__ Bg = &g_Qt[b][0];

    const int wm = (wid & 1) * 64;
    const int wn = (wid >> 1) * 32;

    float acc[4][4][4];
#pragma unroll
    for (int i = 0; i < 4; i++)
#pragma unroll
        for (int j = 0; j < 4; j++)
#pragma unroll
            for (int q = 0; q < 4; q++) acc[i][j][q] = 0.f;

    const uint32_t sA0 = smem_u32(&smA[0]);
    const uint32_t sB0 = smem_u32(&smB[0]);

    // load 128x64 tiles: 1024 chunks of 16B each, 4 per thread per matrix
#pragma unroll
    for (int c = 0; c < 4; c++) {
        const int idx = c * 256 + tid;
        const int row = idx >> 3, cc = idx & 7;
        const uint32_t dA = sA0 + (uint32_t)(row * SCB + cc * 8) * 2;
        const uint32_t dB = sB0 + (uint32_t)(row * SCB + cc * 8) * 2;
        const void* srcA = Ag + (size_t)(m0 + row) * NCQ + cc * 8;
        const void* srcB = Bg + (size_t)(n0 + row) * NCQ + cc * 8;
        asm volatile("cp.async.cg.shared.global [%0], [%1], 16;" :: "r"(dA), "l"(srcA) : "memory");
        asm volatile("cp.async.cg.shared.global [%0], [%1], 16;" :: "r"(dB), "l"(srcB) : "memory");
    }
    asm volatile("cp.async.commit_group;" ::: "memory");
    if (tid < 128) cs[tid] = 0.f;
    asm volatile("cp.async.wait_group 0;" ::: "memory");
    __syncthreads();

    const int la_row = wm + (lane & 15);
    const int la_col = (lane >> 4) << 3;
    const uint32_t a_off = sA0 + (uint32_t)(la_row * SCB + la_col) * 2;
    const int lb_row = wn + (lane & 7);
    const int lb_col = ((lane >> 3) & 1) << 3;
    const uint32_t b_off = sB0 + (uint32_t)(lb_row * SCB + lb_col) * 2;

#pragma unroll
    for (int ks = 0; ks < 4; ks++) {
        uint32_t af[4][4];
#pragma unroll
        for (int mt = 0; mt < 4; mt++) {
            const uint32_t addr = a_off + (uint32_t)(ks * 16) * 2 + (uint32_t)(mt * 16 * SCB) * 2;
            asm volatile("ldmatrix.sync.aligned.m8n8.x4.shared.b16 {%0,%1,%2,%3}, [%4];"
                         : "=r"(af[mt][0]), "=r"(af[mt][1]), "=r"(af[mt][2]), "=r"(af[mt][3])
                         : "r"(addr));
        }
        uint32_t bf[4][2];
#pragma unroll
        for (int nt = 0; nt < 4; nt++) {
            const uint32_t addr = b_off + (uint32_t)(ks * 16) * 2 + (uint32_t)(nt * 8 * SCB) * 2;
            asm volatile("ldmatrix.sync.aligned.m8n8.x2.shared.b16 {%0,%1}, [%2];"
                         : "=r"(bf[nt][0]), "=r"(bf[nt][1]) : "r"(addr));
        }
#pragma unroll
        for (int mt = 0; mt < 4; mt++)
#pragma unroll
            for (int nt = 0; nt < 4; nt++) {
                asm volatile(
                    "mma.sync.aligned.m16n8k16.row.col.f32.bf16.bf16.f32 "
                    "{%0,%1,%2,%3}, {%4,%5,%6,%7}, {%8,%9}, {%0,%1,%2,%3};"
                    : "+f"(acc[mt][nt][0]), "+f"(acc[mt][nt][1]),
                      "+f"(acc[mt][nt][2]), "+f"(acc[mt][nt][3])
                    : "r"(af[mt][0]), "r"(af[mt][1]), "r"(af[mt][2]), "r"(af[mt][3]),
                      "r"(bf[nt][0]), "r"(bf[nt][1]));
            }
    }

    // epilogue: exp, store bf16, accumulate column partial sums
    __nv_bfloat16* __restrict__ E = &g_Et[zz][0];
    const int erow = lane >> 2;
    const int ecol = (lane & 3) * 2;
#pragma unroll
    for (int nt = 0; nt < 4; nt++) {
        const int cl = wn + nt * 8 + ecol;
        float s0 = 0.f, s1 = 0.f;
#pragma unroll
        for (int mt = 0; mt < 4; mt++) {
            const int r0 = m0 + wm + mt * 16 + erow;
            float e0 = __expf(acc[mt][nt][0]);
            float e1 = __expf(acc[mt][nt][1]);
            float e2 = __expf(acc[mt][nt][2]);
            float e3 = __expf(acc[mt][nt][3]);
            *(__nv_bfloat162*)(E + (size_t)r0 * NPIX + n0 + cl)       = __floats2bfloat162_rn(e0, e1);
            *(__nv_bfloat162*)(E + (size_t)(r0 + 8) * NPIX + n0 + cl) = __floats2bfloat162_rn(e2, e3);
            s0 += e0 + e2;
            s1 += e1 + e3;
        }
        atomicAdd(&cs[cl], s0);
        atomicAdd(&cs[cl + 1], s1);
    }
    __syncthreads();
    if (tid < 128) atomicAdd(&g_Zsum[zz][n0 + tid], cs[tid]);
}

// ===================== Zsum init / invert =====================
__global__ __launch_bounds__(1024) void zeroZ_kernel()
{
    const int zz = blockIdx.x;
#pragma unroll
    for (int k = 0; k < 4; k++) g_Zsum[zz][threadIdx.x + k * 1024] = 0.f;
}

__global__ __launch_bounds__(1024) void invertZ_kernel()
{
    const int zz = blockIdx.x;
#pragma unroll
    for (int k = 0; k < 4; k++) {
        const int i = threadIdx.x + k * 1024;
        g_invZ[zz][i] = 1.0f / g_Zsum[zz][i];
    }
}

// ===================== A = bf16(V * invZ), [NC, KTOT] per batch =====================
__global__ __launch_bounds__(256) void convertA_kernel()
{
    // grid (6, 512, 2)
    const int b = blockIdx.z, c = blockIdx.y;
    const int base = blockIdx.x * 2048 + threadIdx.x * 8;  // col in [0, 12288)
    const int br = base >> 12;
    const int i = base & 4095;
    const float* Vp = &g_V[b][0] + (size_t)c * NPIX + i;
    const float* iz = &g_invZ[br * 2 + b][0] + i;
    float4 v0 = *(const float4*)Vp, v1 = *(const float4*)(Vp + 4);
    float4 z0 = *(const float4*)iz, z1 = *(const float4*)(iz + 4);
    union { __nv_bfloat162 h2[4]; uint4 v; } t;
    t.h2[0] = __floats2bfloat162_rn(v0.x * z0.x, v0.y * z0.y);
    t.h2[1] = __floats2bfloat162_rn(v0.z * z0.z, v0.w * z0.w);
    t.h2[2] = __floats2bfloat162_rn(v1.x * z1.x, v1.y * z1.y);
    t.h2[3] = __floats2bfloat162_rn(v1.z * z1.z, v1.w * z1.w);
    *(uint4*)(&g_Abf[b][0] + (size_t)c * KTOT + base) = t.v;
}

// =====================================================================
// Aggregation GEMM on HMMA (mma.sync bf16):
//   att[b][c][n] = sum_k Abf[b][c][k] * Et[.][n][k]   (k over 3*4096)
// Block 128x128, BK=32, 8 warps (2x4), warp tile 64x32.
// Padded SMEM stride 40 bf16 -> conflict-free ldmatrix.
// cp.async double-buffered. grid (32, 4, NB), 256 threads.
// =====================================================================
#define SA 40

__global__ __launch_bounds__(256, 2) void attn_mma_kernel()
{
    __shared__ __nv_bfloat16 smA[2][128 * SA];
    __shared__ __nv_bfloat16 smB[2][128 * SA];

    const int tid = threadIdx.x;
    const int wid = tid >> 5, lane = tid & 31;
    const int b = blockIdx.z;
    const int m0 = blockIdx.y * 128;
    const int n0 = blockIdx.x * 128;

    const __nv_bfloat16* __restrict__ Ag = &g_Abf[b][0];

    const int wm = (wid & 1) * 64;
    const int wn = (wid >> 1) * 32;

    float acc[4][4][4];
#pragma unroll
    for (int i = 0; i < 4; i++)
#pragma unroll
        for (int j = 0; j < 4; j++)
#pragma unroll
            for (int q = 0; q < 4; q++) acc[i][j][q] = 0.f;

    const uint32_t sA0 = smem_u32(&smA[0][0]);
    const uint32_t sB0 = smem_u32(&smB[0][0]);

    const int row0 = tid >> 2;
    const int cc0  = tid & 3;

    const int la_row = wm + (lane & 15);
    const int la_col = (lane >> 4) << 3;
    const uint32_t a_off = (uint32_t)(la_row * SA + la_col) * 2;
    const int lb_row = wn + (lane & 7);
    const int lb_col = ((lane >> 3) & 1) << 3;
    const uint32_t b_off = (uint32_t)(lb_row * SA + lb_col) * 2;

    const int NT = KTOT / 32;  // 384

    {
        const __nv_bfloat16* Bg = &g_Et[b][0];
#pragma unroll
        for (int h = 0; h < 2; h++) {
            const int row = row0 + h * 64;
            const uint32_t dA = sA0 + (uint32_t)(row * SA + cc0 * 8) * 2;
            const uint32_t dB = sB0 + (uint32_t)(row * SA + cc0 * 8) * 2;
            const void* srcA = Ag + (size_t)(m0 + row) * KTOT + cc0 * 8;
            const void* srcB = Bg + (size_t)(n0 + row) * NPIX + cc0 * 8;
            asm volatile("cp.async.cg.shared.global [%0], [%1], 16;" :: "r"(dA), "l"(srcA) : "memory");
            asm volatile("cp.async.cg.shared.global [%0], [%1], 16;" :: "r"(dB), "l"(srcB) : "memory");
        }
        asm volatile("cp.async.commit_group;" ::: "memory");
    }

    for (int kt = 0; kt < NT; ++kt) {
        const int s = kt & 1;
        if (kt + 1 < NT) {
            const int kg = (kt + 1) << 5;
            const int br = kg >> 12;
            const int kloc = kg & 4095;
            const __nv_bfloat16* __restrict__ Bg = &g_Et[br * 2 + b][0];
            const uint32_t stoff = (uint32_t)((s ^ 1) * 128 * SA * 2);
#pragma unroll
            for (int h = 0; h < 2; h++) {
                const int row = row0 + h * 64;
                const uint32_t dA = sA0 + stoff + (uint32_t)(row * SA + cc0 * 8) * 2;
                const uint32_t dB = sB0 + stoff + (uint32_t)(row * SA + cc0 * 8) * 2;
                const void* srcA = Ag + (size_t)(m0 + row) * KTOT + kg + cc0 * 8;
                const void* srcB = Bg + (size_t)(n0 + row) * NPIX + kloc + cc0 * 8;
                asm volatile("cp.async.cg.shared.global [%0], [%1], 16;" :: "r"(dA), "l"(srcA) : "memory");
                asm volatile("cp.async.cg.shared.global [%0], [%1], 16;" :: "r"(dB), "l"(srcB) : "memory");
            }
            asm volatile("cp.async.commit_group;" ::: "memory");
            asm volatile("cp.async.wait_group 1;" ::: "memory");
        } else {
            asm volatile("cp.async.wait_group 0;" ::: "memory");
        }
        __syncthreads();

        const uint32_t stA = sA0 + (uint32_t)(s * 128 * SA * 2);
        const uint32_t stB = sB0 + (uint32_t)(s * 128 * SA * 2);

#pragma unroll
        for (int ks = 0; ks < 2; ks++) {
            uint32_t af[4][4];
#pragma unroll
            for (int mt = 0; mt < 4; mt++) {
                const uint32_t addr = stA + a_off + (uint32_t)(ks * 16) * 2 + (uint32_t)(mt * 16 * SA) * 2;
                asm volatile("ldmatrix.sync.aligned.m8n8.x4.shared.b16 {%0,%1,%2,%3}, [%4];"
                             : "=r"(af[mt][0]), "=r"(af[mt][1]), "=r"(af[mt][2]), "=r"(af[mt][3])
                             : "r"(addr));
            }
            uint32_t bf[4][2];
#pragma unroll
            for (int nt = 0; nt < 4; nt++) {
                const uint32_t addr = stB + b_off + (uint32_t)(ks * 16) * 2 + (uint32_t)(nt * 8 * SA) * 2;
                asm volatile("ldmatrix.sync.aligned.m8n8.x2.shared.b16 {%0,%1}, [%2];"
                             : "=r"(bf[nt][0]), "=r"(bf[nt][1]) : "r"(addr));
            }
#pragma unroll
            for (int mt = 0; mt < 4; mt++)
#pragma unroll
                for (int nt = 0; nt < 4; nt++) {
                    asm volatile(
                        "mma.sync.aligned.m16n8k16.row.col.f32.bf16.bf16.f32 "
                        "{%0,%1,%2,%3}, {%4,%5,%6,%7}, {%8,%9}, {%0,%1,%2,%3};"
                        : "+f"(acc[mt][nt][0]), "+f"(acc[mt][nt][1]),
                          "+f"(acc[mt][nt][2]), "+f"(acc[mt][nt][3])
                        : "r"(af[mt][0]), "r"(af[mt][1]), "r"(af[mt][2]), "r"(af[mt][3]),
                          "r"(bf[nt][0]), "r"(bf[nt][1]));
                }
        }
        __syncthreads();
    }

    float* __restrict__ att = &g_att[b][0];
    const int erow = lane >> 2;
    const int ecol = (lane & 3) * 2;
#pragma unroll
    for (int mt = 0; mt < 4; mt++) {
#pragma unroll
        for (int nt = 0; nt < 4; nt++) {
            const int r0 = m0 + wm + mt * 16 + erow;
            const int c0 = n0 + wn + nt * 8 + ecol;
            *(float2*)(att + (size_t)r0 * NPIX + c0)       = make_float2(acc[mt][nt][0], acc[mt][nt][1]);
            *(float2*)(att + (size_t)(r0 + 8) * NPIX + c0) = make_float2(acc[mt][nt][2], acc[mt][nt][3]);
        }
    }
}

// =====================================================================
// out = x + gamma * (Wl @ att + bl). M=512, N=4096, K=512. grid (32, 4, NB)
// =====================================================================
__global__ __launch_bounds__(256) void final_kernel(
    const float* __restrict__ Wl, const float* __restrict__ bl,
    const float* __restrict__ xin, const float* __restrict__ gamma,
    float* __restrict__ out)
{
    const int b = blockIdx.z;
    const int m0 = blockIdx.y * 128;
    const int n0 = blockIdx.x * 128;
    const float* __restrict__ Att = &g_att[b][0];

    __shared__ float As[8][128];
    __shared__ float Bs[8][128];

    const int tx = threadIdx.x;
    const int trow = tx >> 4, tcol = tx & 15;
    const int ar = tx >> 1, ac = (tx & 1) << 2;
    const int lr = tx >> 5, lc = (tx & 31) << 2;

    float acc[8][8] = {};
    for (int k0 = 0; k0 < NC; k0 += 8) {
        float4 av = *(const float4*)(Wl + (size_t)(m0 + ar) * NC + k0 + ac);
        As[ac + 0][ar] = av.x; As[ac + 1][ar] = av.y;
        As[ac + 2][ar] = av.z; As[ac + 3][ar] = av.w;
        *(float4*)&Bs[lr][lc] = *(const float4*)(Att + (size_t)(k0 + lr) * NPIX + n0 + lc);
        __syncthreads();
#pragma unroll
        for (int kk = 0; kk < 8; kk++) {
            float a[8], bb[8];
            *(float4*)&a[0]  = *(const float4*)&As[kk][trow * 8];
            *(float4*)&a[4]  = *(const float4*)&As[kk][trow * 8 + 4];
            *(float4*)&bb[0] = *(const float4*)&Bs[kk][tcol * 8];
            *(float4*)&bb[4] = *(const float4*)&Bs[kk][tcol * 8 + 4];
#pragma unroll
            for (int i = 0; i < 8; i++)
#pragma unroll
                for (int j = 0; j < 8; j++) acc[i][j] += a[i] * bb[j];
        }
        __syncthreads();
    }

    const float g = gamma[0];
#pragma unroll
    for (int i = 0; i < 8; i++) {
        const int row = m0 + trow * 8 + i;
        const float bs = bl[row];
        const size_t base = (size_t)b * NC * NPIX + (size_t)row * NPIX + n0 + tcol * 8;
        float4 x0 = *(const float4*)(xin + base);
        float4 x1 = *(const float4*)(xin + base + 4);
        *(float4*)(out + base) = make_float4(
            x0.x + g * (acc[i][0] + bs), x0.y + g * (acc[i][1] + bs),
            x0.z + g * (acc[i][2] + bs), x0.w + g * (acc[i][3] + bs));
        *(float4*)(out + base + 4) = make_float4(
            x1.x + g * (acc[i][4] + bs), x1.y + g * (acc[i][5] + bs),
            x1.z + g * (acc[i][6] + bs), x1.w + g * (acc[i][7] + bs));
    }
}

// =====================================================================
extern "C" void kernel_launch(void* const* d_in, const int* in_sizes, int n_in,
                              void* d_out, int out_size)
{
    const float* x   = (const float*)d_in[0];
    const float* y   = (const float*)d_in[1];
    const float* zz  = (const float*)d_in[2];
    const float* Wq  = (const float*)d_in[3];
    const float* bq  = (const float*)d_in[4];
    const float* Wk1 = (const float*)d_in[5];
    const float* bk1 = (const float*)d_in[6];
    const float* Wk2 = (const float*)d_in[7];
    const float* bk2 = (const float*)d_in[8];
    const float* Wk3 = (const float*)d_in[9];
    const float* bk3 = (const float*)d_in[10];
    const float* Wv  = (const float*)d_in[11];
    const float* bv  = (const float*)d_in[12];
    const float* Wl  = (const float*)d_in[13];
    const float* bl  = (const float*)d_in[14];
    const float* gm  = (const float*)d_in[15];
    float* out = (float*)d_out;

    dim3 blk(256);
    zeroZ_kernel<<<6, 1024>>>();
    proj_qk_kernel<<<dim3(32, 4, NB), blk>>>(Wq, bq, Wk1, bk1, Wk2, bk2, Wk3, bk3, x, y, zz);
    transposeQK_kernel<<<dim3(128, 2, 8), dim3(32, 8)>>>();
    proj_v_kernel <<<dim3(32, 8, NB), blk>>>(Wv, bv, x);
    scores_mma_kernel<<<dim3(32, 32, 6), blk>>>();
    invertZ_kernel<<<6, 1024>>>();
    convertA_kernel<<<dim3(6, 512, NB), blk>>>();
    attn_mma_kernel<<<dim3(32, 4, NB), blk>>>();
    final_kernel  <<<dim3(32, 4, NB), blk>>>(Wl, bl, x, gm, out);
}

// round 7
// speedup vs baseline: 5.6051x; 1.4899x over previous
#include <cuda_runtime.h>
#include <cuda_bf16.h>
#include <cstdint>

#define NB   2
#define NC   512
#define NCQ  64
#define NPIX 4096
#define KTOT 12288   // 3 branches * NPIX

// ---------------- static device scratch (allocation-free) ----------------
__device__ __nv_bfloat16 g_Xt[3][NB][(size_t)NPIX * NC];    // 25 MB  Xt[s][b][pixel][ch]
__device__ __nv_bfloat16 g_Wqk[4 * 64 * NC];                // 256KB  [Wq;Wk1;Wk2;Wk3]
__device__ __nv_bfloat16 g_Wv[NC * NC];                     // 512KB
__device__ __nv_bfloat16 g_Wl[NC * NC];                     // 512KB
__device__ __nv_bfloat16 g_Qt[NB][NPIX * NCQ];              //  1 MB  Qt[i][c]
__device__ __nv_bfloat16 g_Kt[3][NB][NPIX * NCQ];           //  3 MB  Kt[j][c]
__device__ __nv_bfloat16 g_Vbf[NB][(size_t)NC * NPIX];      //  8 MB  V[c][i] bf16
__device__ __nv_bfloat16 g_Et[6][(size_t)NPIX * NPIX];      // 201 MB Et[z][j][i]=exp(S[i][j])
__device__ float g_Zsum[6][NPIX];
__device__ float g_invZ[6][NPIX];
__device__ __nv_bfloat16 g_Abf[NB][(size_t)NC * KTOT];      //  25 MB A[c][br*4096+k] = V*invZ
__device__ __nv_bfloat16 g_attT[NB][(size_t)NPIX * NC];     //  8 MB  attT[n][c]

__device__ __forceinline__ uint32_t smem_u32(const void* p) {
    uint32_t a;
    asm("{ .reg .u64 t; cvta.to.shared.u64 t, %1; cvt.u32.u64 %0, t; }" : "=r"(a) : "l"(p));
    return a;
}

// ===================== weight convert/pack =====================
__global__ __launch_bounds__(256) void convertW_kernel(
    const float* __restrict__ Wq, const float* __restrict__ Wk1,
    const float* __restrict__ Wk2, const float* __restrict__ Wk3,
    const float* __restrict__ Wv, const float* __restrict__ Wl)
{
    const int idx = blockIdx.x * 256 + threadIdx.x;
    if (idx < 131072) {
        const int m = idx >> 9, k = idx & 511;
        const float* W = (m < 64) ? Wq : (m < 128) ? Wk1 : (m < 192) ? Wk2 : Wk3;
        g_Wqk[idx] = __float2bfloat16(W[(m & 63) * NC + k]);
    } else if (idx < 393216) {
        g_Wv[idx - 131072] = __float2bfloat16(Wv[idx - 131072]);
    } else if (idx < 655360) {
        g_Wl[idx - 393216] = __float2bfloat16(Wl[idx - 393216]);
    }
}

// ===================== transpose x/y/z -> bf16 [pixel][512] =====================
__global__ __launch_bounds__(256) void transposeX_kernel(
    const float* __restrict__ x, const float* __restrict__ y, const float* __restrict__ z)
{
    const int p = blockIdx.z;
    const int s = p >> 1, b = p & 1;
    const float* in = ((s == 0) ? x : (s == 1) ? y : z) + (size_t)b * NC * NPIX;
    __nv_bfloat16* out = &g_Xt[s][b][0];

    __shared__ float sm[32][33];
    const int p0 = blockIdx.x * 32;
    const int c0 = blockIdx.y * 32;
    const int tx = threadIdx.x, ty = threadIdx.y;
#pragma unroll
    for (int i = 0; i < 4; i++)
        sm[ty + i * 8][tx] = in[(size_t)(c0 + ty + i * 8) * NPIX + p0 + tx];
    __syncthreads();
#pragma unroll
    for (int i = 0; i < 4; i++)
        out[(size_t)(p0 + ty + i * 8) * NC + c0 + tx] = __float2bfloat16(sm[tx][ty + i * 8]);
}

// =====================================================================
// QK projections via HMMA, write Qt/Kt bf16 transposed directly.
// BM=64, BN=128, K=512, BK=32, 8 warps (2x4), warp tile 32x32.
// grid (32, 4=which, NB)
// =====================================================================
#define SPA 40

__global__ __launch_bounds__(256, 2) void proj_qk_mma(
    const float* __restrict__ bq, const float* __restrict__ bk1,
    const float* __restrict__ bk2, const float* __restrict__ bk3)
{
    __shared__ __nv_bfloat16 smA[2][64 * SPA];
    __shared__ __nv_bfloat16 smB[2][128 * SPA];

    const int tid = threadIdx.x;
    const int wid = tid >> 5, lane = tid & 31;
    const int mblk = blockIdx.y, b = blockIdx.z;
    const int n0 = blockIdx.x * 128;

    const __nv_bfloat16* __restrict__ Ag = g_Wqk + (size_t)mblk * 64 * NC;
    const int src = (mblk < 2) ? 0 : (mblk - 1);
    const __nv_bfloat16* __restrict__ Bg = &g_Xt[src][b][0];
    const float* bias = (mblk == 0) ? bq : (mblk == 1) ? bk1 : (mblk == 2) ? bk2 : bk3;
    __nv_bfloat16* __restrict__ Out = (mblk == 0) ? &g_Qt[b][0] : &g_Kt[mblk - 1][b][0];

    const int wm = (wid & 1) * 32;
    const int wn = (wid >> 1) * 32;

    float acc[2][4][4];
#pragma unroll
    for (int i = 0; i < 2; i++)
#pragma unroll
        for (int j = 0; j < 4; j++)
#pragma unroll
            for (int q = 0; q < 4; q++) acc[i][j][q] = 0.f;

    const uint32_t sA0 = smem_u32(&smA[0][0]);
    const uint32_t sB0 = smem_u32(&smB[0][0]);
    const int row0 = tid >> 2, cc0 = tid & 3;

    const int la_row = wm + (lane & 15);
    const int la_col = (lane >> 4) << 3;
    const uint32_t a_off = (uint32_t)(la_row * SPA + la_col) * 2;
    const int lb_row = wn + (lane & 7);
    const int lb_col = ((lane >> 3) & 1) << 3;
    const uint32_t b_off = (uint32_t)(lb_row * SPA + lb_col) * 2;

    const int NT = NC / 32;  // 16

    {
        const uint32_t dA = sA0 + (uint32_t)(row0 * SPA + cc0 * 8) * 2;
        const void* srcA = Ag + (size_t)row0 * NC + cc0 * 8;
        asm volatile("cp.async.cg.shared.global [%0], [%1], 16;" :: "r"(dA), "l"(srcA) : "memory");
#pragma unroll
        for (int h = 0; h < 2; h++) {
            const int row = row0 + h * 64;
            const uint32_t dB = sB0 + (uint32_t)(row * SPA + cc0 * 8) * 2;
            const void* srcB = Bg + (size_t)(n0 + row) * NC + cc0 * 8;
            asm volatile("cp.async.cg.shared.global [%0], [%1], 16;" :: "r"(dB), "l"(srcB) : "memory");
        }
        asm volatile("cp.async.commit_group;" ::: "memory");
    }

    for (int kt = 0; kt < NT; ++kt) {
        const int s = kt & 1;
        if (kt + 1 < NT) {
            const int kg = (kt + 1) << 5;
            const uint32_t soA = (uint32_t)((s ^ 1) * 64 * SPA * 2);
            const uint32_t soB = (uint32_t)((s ^ 1) * 128 * SPA * 2);
            const uint32_t dA = sA0 + soA + (uint32_t)(row0 * SPA + cc0 * 8) * 2;
            const void* srcA = Ag + (size_t)row0 * NC + kg + cc0 * 8;
            asm volatile("cp.async.cg.shared.global [%0], [%1], 16;" :: "r"(dA), "l"(srcA) : "memory");
#pragma unroll
            for (int h = 0; h < 2; h++) {
                const int row = row0 + h * 64;
                const uint32_t dB = sB0 + soB + (uint32_t)(row * SPA + cc0 * 8) * 2;
                const void* srcB = Bg + (size_t)(n0 + row) * NC + kg + cc0 * 8;
                asm volatile("cp.async.cg.shared.global [%0], [%1], 16;" :: "r"(dB), "l"(srcB) : "memory");
            }
            asm volatile("cp.async.commit_group;" ::: "memory");
            asm volatile("cp.async.wait_group 1;" ::: "memory");
        } else {
            asm volatile("cp.async.wait_group 0;" ::: "memory");
        }
        __syncthreads();

        const uint32_t stA = sA0 + (uint32_t)(s * 64 * SPA * 2);
        const uint32_t stB = sB0 + (uint32_t)(s * 128 * SPA * 2);
#pragma unroll
        for (int ks = 0; ks < 2; ks++) {
            uint32_t af[2][4];
#pragma unroll
            for (int mt = 0; mt < 2; mt++) {
                const uint32_t addr = stA + a_off + (uint32_t)(ks * 16) * 2 + (uint32_t)(mt * 16 * SPA) * 2;
                asm volatile("ldmatrix.sync.aligned.m8n8.x4.shared.b16 {%0,%1,%2,%3}, [%4];"
                             : "=r"(af[mt][0]), "=r"(af[mt][1]), "=r"(af[mt][2]), "=r"(af[mt][3])
                             : "r"(addr));
            }
            uint32_t bf[4][2];
#pragma unroll
            for (int nt = 0; nt < 4; nt++) {
                const uint32_t addr = stB + b_off + (uint32_t)(ks * 16) * 2 + (uint32_t)(nt * 8 * SPA) * 2;
                asm volatile("ldmatrix.sync.aligned.m8n8.x2.shared.b16 {%0,%1}, [%2];"
                             : "=r"(bf[nt][0]), "=r"(bf[nt][1]) : "r"(addr));
            }
#pragma unroll
            for (int mt = 0; mt < 2; mt++)
#pragma unroll
                for (int nt = 0; nt < 4; nt++) {
                    asm volatile(
                        "mma.sync.aligned.m16n8k16.row.col.f32.bf16.bf16.f32 "
                        "{%0,%1,%2,%3}, {%4,%5,%6,%7}, {%8,%9}, {%0,%1,%2,%3};"
                        : "+f"(acc[mt][nt][0]), "+f"(acc[mt][nt][1]),
                          "+f"(acc[mt][nt][2]), "+f"(acc[mt][nt][3])
                        : "r"(af[mt][0]), "r"(af[mt][1]), "r"(af[mt][2]), "r"(af[mt][3]),
                          "r"(bf[nt][0]), "r"(bf[nt][1]));
                }
        }
        __syncthreads();
    }

    const int erow = lane >> 2;
    const int ecol = (lane & 3) * 2;
#pragma unroll
    for (int mt = 0; mt < 2; mt++) {
        const int c = wm + mt * 16 + erow;
        const float b0 = bias[c], b1 = bias[c + 8];
#pragma unroll
        for (int nt = 0; nt < 4; nt++) {
            const int n = n0 + wn + nt * 8 + ecol;
            Out[(size_t)n * NCQ + c]           = __float2bfloat16(acc[mt][nt][0] + b0);
            Out[(size_t)(n + 1) * NCQ + c]     = __float2bfloat16(acc[mt][nt][1] + b0);
            Out[(size_t)n * NCQ + c + 8]       = __float2bfloat16(acc[mt][nt][2] + b1);
            Out[(size_t)(n + 1) * NCQ + c + 8] = __float2bfloat16(acc[mt][nt][3] + b1);
        }
    }
}

// =====================================================================
// V projection via HMMA: Vbf[c][n] bf16. BM=128, grid (32, 4, NB)
// =====================================================================
__global__ __launch_bounds__(256, 2) void proj_v_mma(const float* __restrict__ bv)
{
    __shared__ __nv_bfloat16 smA[2][128 * SPA];
    __shared__ __nv_bfloat16 smB[2][128 * SPA];

    const int tid = threadIdx.x;
    const int wid = tid >> 5, lane = tid & 31;
    const int b = blockIdx.z;
    const int m0 = blockIdx.y * 128;
    const int n0 = blockIdx.x * 128;

    const __nv_bfloat16* __restrict__ Ag = g_Wv;
    const __nv_bfloat16* __restrict__ Bg = &g_Xt[0][b][0];

    const int wm = (wid & 1) * 64;
    const int wn = (wid >> 1) * 32;

    float acc[4][4][4];
#pragma unroll
    for (int i = 0; i < 4; i++)
#pragma unroll
        for (int j = 0; j < 4; j++)
#pragma unroll
            for (int q = 0; q < 4; q++) acc[i][j][q] = 0.f;

    const uint32_t sA0 = smem_u32(&smA[0][0]);
    const uint32_t sB0 = smem_u32(&smB[0][0]);
    const int row0 = tid >> 2, cc0 = tid & 3;

    const int la_row = wm + (lane & 15);
    const int la_col = (lane >> 4) << 3;
    const uint32_t a_off = (uint32_t)(la_row * SPA + la_col) * 2;
    const int lb_row = wn + (lane & 7);
    const int lb_col = ((lane >> 3) & 1) << 3;
    const uint32_t b_off = (uint32_t)(lb_row * SPA + lb_col) * 2;

    const int NT = NC / 32;

    {
#pragma unroll
        for (int h = 0; h < 2; h++) {
            const int row = row0 + h * 64;
            const uint32_t dA = sA0 + (uint32_t)(row * SPA + cc0 * 8) * 2;
            const uint32_t dB = sB0 + (uint32_t)(row * SPA + cc0 * 8) * 2;
            const void* srcA = Ag + (size_t)(m0 + row) * NC + cc0 * 8;
            const void* srcB = Bg + (size_t)(n0 + row) * NC + cc0 * 8;
            asm volatile("cp.async.cg.shared.global [%0], [%1], 16;" :: "r"(dA), "l"(srcA) : "memory");
            asm volatile("cp.async.cg.shared.global [%0], [%1], 16;" :: "r"(dB), "l"(srcB) : "memory");
        }
        asm volatile("cp.async.commit_group;" ::: "memory");
    }

    for (int kt = 0; kt < NT; ++kt) {
        const int s = kt & 1;
        if (kt + 1 < NT) {
            const int kg = (kt + 1) << 5;
            const uint32_t stoff = (uint32_t)((s ^ 1) * 128 * SPA * 2);
#pragma unroll
            for (int h = 0; h < 2; h++) {
                const int row = row0 + h * 64;
                const uint32_t dA = sA0 + stoff + (uint32_t)(row * SPA + cc0 * 8) * 2;
                const uint32_t dB = sB0 + stoff + (uint32_t)(row * SPA + cc0 * 8) * 2;
                const void* srcA = Ag + (size_t)(m0 + row) * NC + kg + cc0 * 8;
                const void* srcB = Bg + (size_t)(n0 + row) * NC + kg + cc0 * 8;
                asm volatile("cp.async.cg.shared.global [%0], [%1], 16;" :: "r"(dA), "l"(srcA) : "memory");
                asm volatile("cp.async.cg.shared.global [%0], [%1], 16;" :: "r"(dB), "l"(srcB) : "memory");
            }
            asm volatile("cp.async.commit_group;" ::: "memory");
            asm volatile("cp.async.wait_group 1;" ::: "memory");
        } else {
            asm volatile("cp.async.wait_group 0;" ::: "memory");
        }
        __syncthreads();

        const uint32_t stA = sA0 + (uint32_t)(s * 128 * SPA * 2);
        const uint32_t stB = sB0 + (uint32_t)(s * 128 * SPA * 2);
#pragma unroll
        for (int ks = 0; ks < 2; ks++) {
            uint32_t af[4][4];
#pragma unroll
            for (int mt = 0; mt < 4; mt++) {
                const uint32_t addr = stA + a_off + (uint32_t)(ks * 16) * 2 + (uint32_t)(mt * 16 * SPA) * 2;
                asm volatile("ldmatrix.sync.aligned.m8n8.x4.shared.b16 {%0,%1,%2,%3}, [%4];"
                             : "=r"(af[mt][0]), "=r"(af[mt][1]), "=r"(af[mt][2]), "=r"(af[mt][3])
                             : "r"(addr));
            }
            uint32_t bf[4][2];
#pragma unroll
            for (int nt = 0; nt < 4; nt++) {
                const uint32_t addr = stB + b_off + (uint32_t)(ks * 16) * 2 + (uint32_t)(nt * 8 * SPA) * 2;
                asm volatile("ldmatrix.sync.aligned.m8n8.x2.shared.b16 {%0,%1}, [%2];"
                             : "=r"(bf[nt][0]), "=r"(bf[nt][1]) : "r"(addr));
            }
#pragma unroll
            for (int mt = 0; mt < 4; mt++)
#pragma unroll
                for (int nt = 0; nt < 4; nt++) {
                    asm volatile(
                        "mma.sync.aligned.m16n8k16.row.col.f32.bf16.bf16.f32 "
                        "{%0,%1,%2,%3}, {%4,%5,%6,%7}, {%8,%9}, {%0,%1,%2,%3};"
                        : "+f"(acc[mt][nt][0]), "+f"(acc[mt][nt][1]),
                          "+f"(acc[mt][nt][2]), "+f"(acc[mt][nt][3])
                        : "r"(af[mt][0]), "r"(af[mt][1]), "r"(af[mt][2]), "r"(af[mt][3]),
                          "r"(bf[nt][0]), "r"(bf[nt][1]));
                }
        }
        __syncthreads();
    }

    __nv_bfloat16* __restrict__ V = &g_Vbf[b][0];
    const int erow = lane >> 2;
    const int ecol = (lane & 3) * 2;
#pragma unroll
    for (int mt = 0; mt < 4; mt++) {
        const int c = m0 + wm + mt * 16 + erow;
        const float b0 = bv[c], b1 = bv[c + 8];
#pragma unroll
        for (int nt = 0; nt < 4; nt++) {
            const int n = n0 + wn + nt * 8 + ecol;
            *(__nv_bfloat162*)(V + (size_t)c * NPIX + n) =
                __floats2bfloat162_rn(acc[mt][nt][0] + b0, acc[mt][nt][1] + b0);
            *(__nv_bfloat162*)(V + (size_t)(c + 8) * NPIX + n) =
                __floats2bfloat162_rn(acc[mt][nt][2] + b1, acc[mt][nt][3] + b1);
        }
    }
}

// =====================================================================
// Scores via HMMA + fused column-sum (unchanged from R6)
// =====================================================================
#define SCB 72

__global__ __launch_bounds__(256, 2) void scores_mma_kernel()
{
    __shared__ __nv_bfloat16 smA[128 * SCB];
    __shared__ __nv_bfloat16 smB[128 * SCB];
    __shared__ float cs[128];

    const int tid = threadIdx.x;
    const int wid = tid >> 5, lane = tid & 31;
    const int zz = blockIdx.z;
    const int b = zz & 1, br = zz >> 1;
    const int m0 = blockIdx.y * 128;
    const int n0 = blockIdx.x * 128;

    const __nv_bfloat16* __restrict__ Ag = &g_Kt[br][b][0];
    const __nv_bfloat16* __restrict__ Bg = &g_Qt[b][0];

    const int wm = (wid & 1) * 64;
    const int wn = (wid >> 1) * 32;

    float acc[4][4][4];
#pragma unroll
    for (int i = 0; i < 4; i++)
#pragma unroll
        for (int j = 0; j < 4; j++)
#pragma unroll
            for (int q = 0; q < 4; q++) acc[i][j][q] = 0.f;

    const uint32_t sA0 = smem_u32(&smA[0]);
    const uint32_t sB0 = smem_u32(&smB[0]);

#pragma unroll
    for (int c = 0; c < 4; c++) {
        const int idx = c * 256 + tid;
        const int row = idx >> 3, cc = idx & 7;
        const uint32_t dA = sA0 + (uint32_t)(row * SCB + cc * 8) * 2;
        const uint32_t dB = sB0 + (uint32_t)(row * SCB + cc * 8) * 2;
        const void* srcA = Ag + (size_t)(m0 + row) * NCQ + cc * 8;
        const void* srcB = Bg + (size_t)(n0 + row) * NCQ + cc * 8;
        asm volatile("cp.async.cg.shared.global [%0], [%1], 16;" :: "r"(dA), "l"(srcA) : "memory");
        asm volatile("cp.async.cg.shared.global [%0], [%1], 16;" :: "r"(dB), "l"(srcB) : "memory");
    }
    asm volatile("cp.async.commit_group;" ::: "memory");
    if (tid < 128) cs[tid] = 0.f;
    asm volatile("cp.async.wait_group 0;" ::: "memory");
    __syncthreads();

    const int la_row = wm + (lane & 15);
    const int la_col = (lane >> 4) << 3;
    const uint32_t a_off = sA0 + (uint32_t)(la_row * SCB + la_col) * 2;
    const int lb_row = wn + (lane & 7);
    const int lb_col = ((lane >> 3) & 1) << 3;
    const uint32_t b_off = sB0 + (uint32_t)(lb_row * SCB + lb_col) * 2;

#pragma unroll
    for (int ks = 0; ks < 4; ks++) {
        uint32_t af[4][4];
#pragma unroll
        for (int mt = 0; mt < 4; mt++) {
            const uint32_t addr = a_off + (uint32_t)(ks * 16) * 2 + (uint32_t)(mt * 16 * SCB) * 2;
            asm volatile("ldmatrix.sync.aligned.m8n8.x4.shared.b16 {%0,%1,%2,%3}, [%4];"
                         : "=r"(af[mt][0]), "=r"(af[mt][1]), "=r"(af[mt][2]), "=r"(af[mt][3])
                         : "r"(addr));
        }
        uint32_t bf[4][2];
#pragma unroll
        for (int nt = 0; nt < 4; nt++) {
            const uint32_t addr = b_off + (uint32_t)(ks * 16) * 2 + (uint32_t)(nt * 8 * SCB) * 2;
            asm volatile("ldmatrix.sync.aligned.m8n8.x2.shared.b16 {%0,%1}, [%2];"
                         : "=r"(bf[nt][0]), "=r"(bf[nt][1]) : "r"(addr));
        }
#pragma unroll
        for (int mt = 0; mt < 4; mt++)
#pragma unroll
            for (int nt = 0; nt < 4; nt++) {
                asm volatile(
                    "mma.sync.aligned.m16n8k16.row.col.f32.bf16.bf16.f32 "
                    "{%0,%1,%2,%3}, {%4,%5,%6,%7}, {%8,%9}, {%0,%1,%2,%3};"
                    : "+f"(acc[mt][nt][0]), "+f"(acc[mt][nt][1]),
                      "+f"(acc[mt][nt][2]), "+f"(acc[mt][nt][3])
                    : "r"(af[mt][0]), "r"(af[mt][1]), "r"(af[mt][2]), "r"(af[mt][3]),
                      "r"(bf[nt][0]), "r"(bf[nt][1]));
            }
    }

    __nv_bfloat16* __restrict__ E = &g_Et[zz][0];
    const int erow = lane >> 2;
    const int ecol = (lane & 3) * 2;
#pragma unroll
    for (int nt = 0; nt < 4; nt++) {
        const int cl = wn + nt * 8 + ecol;
        float s0 = 0.f, s1 = 0.f;
#pragma unroll
        for (int mt = 0; mt < 4; mt++) {
            const int r0 = m0 + wm + mt * 16 + erow;
            float e0 = __expf(acc[mt][nt][0]);
            float e1 = __expf(acc[mt][nt][1]);
            float e2 = __expf(acc[mt][nt][2]);
            float e3 = __expf(acc[mt][nt][3]);
            *(__nv_bfloat162*)(E + (size_t)r0 * NPIX + n0 + cl)       = __floats2bfloat162_rn(e0, e1);
            *(__nv_bfloat162*)(E + (size_t)(r0 + 8) * NPIX + n0 + cl) = __floats2bfloat162_rn(e2, e3);
            s0 += e0 + e2;
            s1 += e1 + e3;
        }
        atomicAdd(&cs[cl], s0);
        atomicAdd(&cs[cl + 1], s1);
    }
    __syncthreads();
    if (tid < 128) atomicAdd(&g_Zsum[zz][n0 + tid], cs[tid]);
}

// ===================== Zsum init / invert =====================
__global__ __launch_bounds__(1024) void zeroZ_kernel()
{
    const int zz = blockIdx.x;
#pragma unroll
    for (int k = 0; k < 4; k++) g_Zsum[zz][threadIdx.x + k * 1024] = 0.f;
}

__global__ __launch_bounds__(1024) void invertZ_kernel()
{
    const int zz = blockIdx.x;
#pragma unroll
    for (int k = 0; k < 4; k++) {
        const int i = threadIdx.x + k * 1024;
        g_invZ[zz][i] = 1.0f / g_Zsum[zz][i];
    }
}

// ===================== A = bf16(V * invZ), from bf16 V =====================
__global__ __launch_bounds__(256) void convertA_kernel()
{
    // grid (6, 512, 2)
    const int b = blockIdx.z, c = blockIdx.y;
    const int base = blockIdx.x * 2048 + threadIdx.x * 8;
    const int br = base >> 12;
    const int i = base & 4095;
    const __nv_bfloat16* Vp = &g_Vbf[b][0] + (size_t)c * NPIX + i;
    const float* iz = &g_invZ[br * 2 + b][0] + i;
    union { __nv_bfloat162 h2[4]; uint4 v; } vi;
    vi.v = *(const uint4*)Vp;
    float4 z0 = *(const float4*)iz, z1 = *(const float4*)(iz + 4);
    union { __nv_bfloat162 h2[4]; uint4 v; } t;
    t.h2[0] = __floats2bfloat162_rn(__bfloat162float(vi.h2[0].x) * z0.x, __bfloat162float(vi.h2[0].y) * z0.y);
    t.h2[1] = __floats2bfloat162_rn(__bfloat162float(vi.h2[1].x) * z0.z, __bfloat162float(vi.h2[1].y) * z0.w);
    t.h2[2] = __floats2bfloat162_rn(__bfloat162float(vi.h2[2].x) * z1.x, __bfloat162float(vi.h2[2].y) * z1.y);
    t.h2[3] = __floats2bfloat162_rn(__bfloat162float(vi.h2[3].x) * z1.z, __bfloat162float(vi.h2[3].y) * z1.w);
    *(uint4*)(&g_Abf[b][0] + (size_t)c * KTOT + base) = t.v;
}

// =====================================================================
// Aggregation GEMM (HMMA), epilogue writes attT[n][c] bf16.
// =====================================================================
#define SA 40

__global__ __launch_bounds__(256, 2) void attn_mma_kernel()
{
    __shared__ __nv_bfloat16 smA[2][128 * SA];
    __shared__ __nv_bfloat16 smB[2][128 * SA];

    const int tid = threadIdx.x;
    const int wid = tid >> 5, lane = tid & 31;
    const int b = blockIdx.z;
    const int m0 = blockIdx.y * 128;
    const int n0 = blockIdx.x * 128;

    const __nv_bfloat16* __restrict__ Ag = &g_Abf[b][0];

    const int wm = (wid & 1) * 64;
    const int wn = (wid >> 1) * 32;

    float acc[4][4][4];
#pragma unroll
    for (int i = 0; i < 4; i++)
#pragma unroll
        for (int j = 0; j < 4; j++)
#pragma unroll
            for (int q = 0; q < 4; q++) acc[i][j][q] = 0.f;

    const uint32_t sA0 = smem_u32(&smA[0][0]);
    const uint32_t sB0 = smem_u32(&smB[0][0]);

    const int row0 = tid >> 2;
    const int cc0  = tid & 3;

    const int la_row = wm + (lane & 15);
    const int la_col = (lane >> 4) << 3;
    const uint32_t a_off = (uint32_t)(la_row * SA + la_col) * 2;
    const int lb_row = wn + (lane & 7);
    const int lb_col = ((lane >> 3) & 1) << 3;
    const uint32_t b_off = (uint32_t)(lb_row * SA + lb_col) * 2;

    const int NT = KTOT / 32;  // 384

    {
        const __nv_bfloat16* Bg = &g_Et[b][0];
#pragma unroll
        for (int h = 0; h < 2; h++) {
            const int row = row0 + h * 64;
            const uint32_t dA = sA0 + (uint32_t)(row * SA + cc0 * 8) * 2;
            const uint32_t dB = sB0 + (uint32_t)(row * SA + cc0 * 8) * 2;
            const void* srcA = Ag + (size_t)(m0 + row) * KTOT + cc0 * 8;
            const void* srcB = Bg + (size_t)(n0 + row) * NPIX + cc0 * 8;
            asm volatile("cp.async.cg.shared.global [%0], [%1], 16;" :: "r"(dA), "l"(srcA) : "memory");
            asm volatile("cp.async.cg.shared.global [%0], [%1], 16;" :: "r"(dB), "l"(srcB) : "memory");
        }
        asm volatile("cp.async.commit_group;" ::: "memory");
    }

    for (int kt = 0; kt < NT; ++kt) {
        const int s = kt & 1;
        if (kt + 1 < NT) {
            const int kg = (kt + 1) << 5;
            const int br = kg >> 12;
            const int kloc = kg & 4095;
            const __nv_bfloat16* __restrict__ Bg = &g_Et[br * 2 + b][0];
            const uint32_t stoff = (uint32_t)((s ^ 1) * 128 * SA * 2);
#pragma unroll
            for (int h = 0; h < 2; h++) {
                const int row = row0 + h * 64;
                const uint32_t dA = sA0 + stoff + (uint32_t)(row * SA + cc0 * 8) * 2;
                const uint32_t dB = sB0 + stoff + (uint32_t)(row * SA + cc0 * 8) * 2;
                const void* srcA = Ag + (size_t)(m0 + row) * KTOT + kg + cc0 * 8;
                const void* srcB = Bg + (size_t)(n0 + row) * NPIX + kloc + cc0 * 8;
                asm volatile("cp.async.cg.shared.global [%0], [%1], 16;" :: "r"(dA), "l"(srcA) : "memory");
                asm volatile("cp.async.cg.shared.global [%0], [%1], 16;" :: "r"(dB), "l"(srcB) : "memory");
            }
            asm volatile("cp.async.commit_group;" ::: "memory");
            asm volatile("cp.async.wait_group 1;" ::: "memory");
        } else {
            asm volatile("cp.async.wait_group 0;" ::: "memory");
        }
        __syncthreads();

        const uint32_t stA = sA0 + (uint32_t)(s * 128 * SA * 2);
        const uint32_t stB = sB0 + (uint32_t)(s * 128 * SA * 2);

#pragma unroll
        for (int ks = 0; ks < 2; ks++) {
            uint32_t af[4][4];
#pragma unroll
            for (int mt = 0; mt < 4; mt++) {
                const uint32_t addr = stA + a_off + (uint32_t)(ks * 16) * 2 + (uint32_t)(mt * 16 * SA) * 2;
                asm volatile("ldmatrix.sync.aligned.m8n8.x4.shared.b16 {%0,%1,%2,%3}, [%4];"
                             : "=r"(af[mt][0]), "=r"(af[mt][1]), "=r"(af[mt][2]), "=r"(af[mt][3])
                             : "r"(addr));
            }
            uint32_t bf[4][2];
#pragma unroll
            for (int nt = 0; nt < 4; nt++) {
                const uint32_t addr = stB + b_off + (uint32_t)(ks * 16) * 2 + (uint32_t)(nt * 8 * SA) * 2;
                asm volatile("ldmatrix.sync.aligned.m8n8.x2.shared.b16 {%0,%1}, [%2];"
                             : "=r"(bf[nt][0]), "=r"(bf[nt][1]) : "r"(addr));
            }
#pragma unroll
            for (int mt = 0; mt < 4; mt++)
#pragma unroll
                for (int nt = 0; nt < 4; nt++) {
                    asm volatile(
                        "mma.sync.aligned.m16n8k16.row.col.f32.bf16.bf16.f32 "
                        "{%0,%1,%2,%3}, {%4,%5,%6,%7}, {%8,%9}, {%0,%1,%2,%3};"
                        : "+f"(acc[mt][nt][0]), "+f"(acc[mt][nt][1]),
                          "+f"(acc[mt][nt][2]), "+f"(acc[mt][nt][3])
                        : "r"(af[mt][0]), "r"(af[mt][1]), "r"(af[mt][2]), "r"(af[mt][3]),
                          "r"(bf[nt][0]), "r"(bf[nt][1]));
                }
        }
        __syncthreads();
    }

    __nv_bfloat16* __restrict__ at = &g_attT[b][0];
    const int erow = lane >> 2;
    const int ecol = (lane & 3) * 2;
#pragma unroll
    for (int mt = 0; mt < 4; mt++) {
#pragma unroll
        for (int nt = 0; nt < 4; nt++) {
            const int m = m0 + wm + mt * 16 + erow;
            const int n = n0 + wn + nt * 8 + ecol;
            at[(size_t)n * NC + m]           = __float2bfloat16(acc[mt][nt][0]);
            at[(size_t)(n + 1) * NC + m]     = __float2bfloat16(acc[mt][nt][1]);
            at[(size_t)n * NC + m + 8]       = __float2bfloat16(acc[mt][nt][2]);
            at[(size_t)(n + 1) * NC + m + 8] = __float2bfloat16(acc[mt][nt][3]);
        }
    }
}

// =====================================================================
// Final via HMMA: out[c][n] = x + gamma*(Wl@att + bl). grid (32, 4, NB)
// =====================================================================
__global__ __launch_bounds__(256, 2) void final_mma(
    const float* __restrict__ bl, const float* __restrict__ xin,
    const float* __restrict__ gamma, float* __restrict__ out)
{
    __shared__ __nv_bfloat16 smA[2][128 * SPA];
    __shared__ __nv_bfloat16 smB[2][128 * SPA];

    const int tid = threadIdx.x;
    const int wid = tid >> 5, lane = tid & 31;
    const int b = blockIdx.z;
    const int m0 = blockIdx.y * 128;
    const int n0 = blockIdx.x * 128;

    const __nv_bfloat16* __restrict__ Ag = g_Wl;
    const __nv_bfloat16* __restrict__ Bg = &g_attT[b][0];

    const int wm = (wid & 1) * 64;
    const int wn = (wid >> 1) * 32;

    float acc[4][4][4];
#pragma unroll
    for (int i = 0; i < 4; i++)
#pragma unroll
        for (int j = 0; j < 4; j++)
#pragma unroll
            for (int q = 0; q < 4; q++) acc[i][j][q] = 0.f;

    const uint32_t sA0 = smem_u32(&smA[0][0]);
    const uint32_t sB0 = smem_u32(&smB[0][0]);
    const int row0 = tid >> 2, cc0 = tid & 3;

    const int la_row = wm + (lane & 15);
    const int la_col = (lane >> 4) << 3;
    const uint32_t a_off = (uint32_t)(la_row * SPA + la_col) * 2;
    const int lb_row = wn + (lane & 7);
    const int lb_col = ((lane >> 3) & 1) << 3;
    const uint32_t b_off = (uint32_t)(lb_row * SPA + lb_col) * 2;

    const int NT = NC / 32;

    {
#pragma unroll
        for (int h = 0; h < 2; h++) {
            const int row = row0 + h * 64;
            const uint32_t dA = sA0 + (uint32_t)(row * SPA + cc0 * 8) * 2;
            const uint32_t dB = sB0 + (uint32_t)(row * SPA + cc0 * 8) * 2;
            const void* srcA = Ag + (size_t)(m0 + row) * NC + cc0 * 8;
            const void* srcB = Bg + (size_t)(n0 + row) * NC + cc0 * 8;
            asm volatile("cp.async.cg.shared.global [%0], [%1], 16;" :: "r"(dA), "l"(srcA) : "memory");
            asm volatile("cp.async.cg.shared.global [%0], [%1], 16;" :: "r"(dB), "l"(srcB) : "memory");
        }
        asm volatile("cp.async.commit_group;" ::: "memory");
    }

    for (int kt = 0; kt < NT; ++kt) {
        const int s = kt & 1;
        if (kt + 1 < NT) {
            const int kg = (kt + 1) << 5;
            const uint32_t stoff = (uint32_t)((s ^ 1) * 128 * SPA * 2);
#pragma unroll
            for (int h = 0; h < 2; h++) {
                const int row = row0 + h * 64;
                const uint32_t dA = sA0 + stoff + (uint32_t)(row * SPA + cc0 * 8) * 2;
                const uint32_t dB = sB0 + stoff + (uint32_t)(row * SPA + cc0 * 8) * 2;
                const void* srcA = Ag + (size_t)(m0 + row) * NC + kg + cc0 * 8;
                const void* srcB = Bg + (size_t)(n0 + row) * NC + kg + cc0 * 8;
                asm volatile("cp.async.cg.shared.global [%0], [%1], 16;" :: "r"(dA), "l"(srcA) : "memory");
                asm volatile("cp.async.cg.shared.global [%0], [%1], 16;" :: "r"(dB), "l"(srcB) : "memory");
            }
            asm volatile("cp.async.commit_group;" ::: "memory");
            asm volatile("cp.async.wait_group 1;" ::: "memory");
        } else {
            asm volatile("cp.async.wait_group 0;" ::: "memory");
        }
        __syncthreads();

        const uint32_t stA = sA0 + (uint32_t)(s * 128 * SPA * 2);
        const uint32_t stB = sB0 + (uint32_t)(s * 128 * SPA * 2);
#pragma unroll
        for (int ks = 0; ks < 2; ks++) {
            uint32_t af[4][4];
#pragma unroll
            for (int mt = 0; mt < 4; mt++) {
                const uint32_t addr = stA + a_off + (uint32_t)(ks * 16) * 2 + (uint32_t)(mt * 16 * SPA) * 2;
                asm volatile("ldmatrix.sync.aligned.m8n8.x4.shared.b16 {%0,%1,%2,%3}, [%4];"
                             : "=r"(af[mt][0]), "=r"(af[mt][1]), "=r"(af[mt][2]), "=r"(af[mt][3])
                             : "r"(addr));
            }
            uint32_t bf[4][2];
#pragma unroll
            for (int nt = 0; nt < 4; nt++) {
                const uint32_t addr = stB + b_off + (uint32_t)(ks * 16) * 2 + (uint32_t)(nt * 8 * SPA) * 2;
                asm volatile("ldmatrix.sync.aligned.m8n8.x2.shared.b16 {%0,%1}, [%2];"
                             : "=r"(bf[nt][0]), "=r"(bf[nt][1]) : "r"(addr));
            }
#pragma unroll
            for (int mt = 0; mt < 4; mt++)
#pragma unroll
                for (int nt = 0; nt < 4; nt++) {
                    asm volatile(
                        "mma.sync.aligned.m16n8k16.row.col.f32.bf16.bf16.f32 "
                        "{%0,%1,%2,%3}, {%4,%5,%6,%7}, {%8,%9}, {%0,%1,%2,%3};"
                        : "+f"(acc[mt][nt][0]), "+f"(acc[mt][nt][1]),
                          "+f"(acc[mt][nt][2]), "+f"(acc[mt][nt][3])
                        : "r"(af[mt][0]), "r"(af[mt][1]), "r"(af[mt][2]), "r"(af[mt][3]),
                          "r"(bf[nt][0]), "r"(bf[nt][1]));
                }
        }
        __syncthreads();
    }

    const float g = gamma[0];
    const int erow = lane >> 2;
    const int ecol = (lane & 3) * 2;
#pragma unroll
    for (int mt = 0; mt < 4; mt++) {
        const int c = m0 + wm + mt * 16 + erow;
        const float b0 = bl[c], b1 = bl[c + 8];
#pragma unroll
        for (int nt = 0; nt < 4; nt++) {
            const int n = n0 + wn + nt * 8 + ecol;
            const size_t base0 = (size_t)b * NC * NPIX + (size_t)c * NPIX + n;
            const size_t base1 = (size_t)b * NC * NPIX + (size_t)(c + 8) * NPIX + n;
            float2 x0 = *(const float2*)(xin + base0);
            float2 x1 = *(const float2*)(xin + base1);
            *(float2*)(out + base0) = make_float2(x0.x + g * (acc[mt][nt][0] + b0),
                                                  x0.y + g * (acc[mt][nt][1] + b0));
            *(float2*)(out + base1) = make_float2(x1.x + g * (acc[mt][nt][2] + b1),
                                                  x1.y + g * (acc[mt][nt][3] + b1));
        }
    }
}

// =====================================================================
extern "C" void kernel_launch(void* const* d_in, const int* in_sizes, int n_in,
                              void* d_out, int out_size)
{
    const float* x   = (const float*)d_in[0];
    const float* y   = (const float*)d_in[1];
    const float* zz  = (const float*)d_in[2];
    const float* Wq  = (const float*)d_in[3];
    const float* bq  = (const float*)d_in[4];
    const float* Wk1 = (const float*)d_in[5];
    const float* bk1 = (const float*)d_in[6];
    const float* Wk2 = (const float*)d_in[7];
    const float* bk2 = (const float*)d_in[8];
    const float* Wk3 = (const float*)d_in[9];
    const float* bk3 = (const float*)d_in[10];
    const float* Wv  = (const float*)d_in[11];
    const float* bv  = (const float*)d_in[12];
    const float* Wl  = (const float*)d_in[13];
    const float* bl  = (const float*)d_in[14];
    const float* gm  = (const float*)d_in[15];
    float* out = (float*)d_out;

    dim3 blk(256);
    zeroZ_kernel<<<6, 1024>>>();
    convertW_kernel<<<2560, blk>>>(Wq, Wk1, Wk2, Wk3, Wv, Wl);
    transposeX_kernel<<<dim3(128, 16, 6), dim3(32, 8)>>>(x, y, zz);
    proj_qk_mma<<<dim3(32, 4, NB), blk>>>(bq, bk1, bk2, bk3);
    proj_v_mma <<<dim3(32, 4, NB), blk>>>(bv);
    scores_mma_kernel<<<dim3(32, 32, 6), blk>>>();
    invertZ_kernel<<<6, 1024>>>();
    convertA_kernel<<<dim3(6, 512, NB), blk>>>();
    attn_mma_kernel<<<dim3(32, 4, NB), blk>>>();
    final_mma<<<dim3(32, 4, NB), blk>>>(bl, x, gm, out);
}